// round 6
// baseline (speedup 1.0000x reference)
#include <cuda_runtime.h>
#include <cuda_fp16.h>
#include <cstdint>

#define NROWS   131072
#define HD      128
#define NSTEPS  12
#define MROWS   64
#define NBLK    (NROWS / MROWS)
#define NTHREADS 256
#define HS_STRIDE ((size_t)NROWS * HD)
#define LO_SCALE   1024.0f
#define LO_INV     (1.0f / 1024.0f)

// ---------------- SMEM layout (byte offsets) -------------------------------
// Big tiles: rows x 512 bytes (256 fp16), 16B-chunk swizzle: chunk ^= (row&7)
#define OFF_WH   0        // W hi fp16: 128(n) x 256(k)     64 KB
#define OFF_WL   65536    // W lo*1024 fp16                 64 KB
#define OFF_FH   131072   // feats hi fp16: 64(m) x 256(k)  32 KB
#define OFF_FL   163840   // feats lo*1024 fp16             32 KB
#define OFF_EW   196608
#define OFF_EB   197120
#define OFF_DB   197632
#define OFF_RW   198144   // 3*128 floats
#define OFF_OUT  199680   // 64 floats
#define OFF_RB   199936
#define SMEM_TOTAL 200704

// ======================= low-level helpers =================================
static __device__ __forceinline__ uint32_t smem_u32(const void* p) {
    uint32_t a;
    asm("{ .reg .u64 t; cvta.to.shared.u64 t, %1; cvt.u32.u64 %0, t; }" : "=r"(a) : "l"(p));
    return a;
}
static __device__ __forceinline__ void ldmx4(uint32_t* a, uint32_t addr) {
    asm volatile("ldmatrix.sync.aligned.m8n8.x4.shared.b16 {%0,%1,%2,%3}, [%4];"
                 : "=r"(a[0]), "=r"(a[1]), "=r"(a[2]), "=r"(a[3]) : "r"(addr));
}
static __device__ __forceinline__ void mma16816(float* c, const uint32_t* a, const uint32_t* b) {
    asm volatile("mma.sync.aligned.m16n8k16.row.col.f32.f16.f16.f32 "
                 "{%0,%1,%2,%3}, {%4,%5,%6,%7}, {%8,%9}, {%0,%1,%2,%3};"
                 : "+f"(c[0]), "+f"(c[1]), "+f"(c[2]), "+f"(c[3])
                 : "r"(a[0]), "r"(a[1]), "r"(a[2]), "r"(a[3]), "r"(b[0]), "r"(b[1]));
}

// hi/lo fp16 split of a pair; lo scaled by LO_SCALE (keeps lo in fp16 normal range)
static __device__ __forceinline__ void split2(float a, float b, uint32_t& hi, uint32_t& lo) {
    __half ha = __float2half_rn(a), hb = __float2half_rn(b);
    float ra = (a - __half2float(ha)) * LO_SCALE;
    float rb = (b - __half2float(hb)) * LO_SCALE;
    hi = (uint32_t)__half_as_ushort(ha) | ((uint32_t)__half_as_ushort(hb) << 16);
    lo = (uint32_t)__half_as_ushort(__float2half_rn(ra)) |
         ((uint32_t)__half_as_ushort(__float2half_rn(rb)) << 16);
}

// 4B store into a swizzled 512B-row tile
static __device__ __forceinline__ void st4sw(char* sm, int off, int r, int cbyte, uint32_t v) {
    uint32_t chunk = ((uint32_t)(cbyte >> 4)) ^ (uint32_t)(r & 7);
    *(uint32_t*)(sm + off + r * 512 + (chunk << 4) + (cbyte & 15)) = v;
}

// Write cos/sin (hi + scaled lo) for row r, columns cj, cj+1.
// cos -> k = cj (byte 2*cj), sin -> k = 128+cj (byte 256+2*cj)
static __device__ __forceinline__ void emit_feats(char* sm, int r, int cj,
                                                  float c0, float c1, float s0, float s1) {
    uint32_t chi, clo, shi, slo;
    split2(c0, c1, chi, clo);
    split2(s0, s1, shi, slo);
    st4sw(sm, OFF_FH, r, 2 * cj, chi);
    st4sw(sm, OFF_FH, r, 256 + 2 * cj, shi);
    st4sw(sm, OFF_FL, r, 2 * cj, clo);
    st4sw(sm, OFF_FL, r, 256 + 2 * cj, slo);
}

// Stage 128x256 fp32 weight block (d_w cols [colbase, colbase+256)) as fp16
// hi + scaled-lo into OFF_WH/OFF_WL with the swizzled layout. 256 threads:
// thread = (row r = tid>>1, k-half = tid&1).
static __device__ __forceinline__ void stage_w(char* sm, const float* __restrict__ dw,
                                               int colbase, int tid) {
    int r = tid >> 1, half = tid & 1;
    const float4* src = (const float4*)(dw + (size_t)r * 512 + colbase + 128 * half);
    int rx = r & 7;
    char* dh = sm + OFF_WH + r * 512;
    char* dl = sm + OFF_WL + r * 512;
#pragma unroll
    for (int i = 0; i < 16; i++) {
        float4 v0 = src[2 * i];
        float4 v1 = src[2 * i + 1];
        uint4 h, l;
        split2(v0.x, v0.y, h.x, l.x);
        split2(v0.z, v0.w, h.y, l.y);
        split2(v1.x, v1.y, h.z, l.z);
        split2(v1.z, v1.w, h.w, l.w);
        uint32_t chunk = (uint32_t)((half * 16 + i) ^ rx);
        *(uint4*)(dh + (chunk << 4)) = h;
        *(uint4*)(dl + (chunk << 4)) = l;
    }
}

// 3-pass split GEMM: C += Ah@Wh^T + (Al@Wh^T + Ah@Wl^T)/1024. K=256, tile 16x64.
static __device__ __forceinline__ void gemm3(float* C, uint32_t sb, int lane,
                                             int Rbase, int n0) {
    float Cw[32];
#pragma unroll
    for (int i = 0; i < 32; i++) Cw[i] = 0.f;
    const int r   = Rbase + (lane & 7) + ((lane >> 3) & 1) * 8;
    const int rx  = lane & 7;
    const int kpa = lane >> 4;                   // A: k-chunk parity per lane group
    const int kpb = (lane >> 3) & 1;             // B: k-chunk parity
    const int jb  = (lane >> 4) & 1;             // B: j within the j-pair
    const uint32_t aH = sb + OFF_FH + r * 512;
    const uint32_t aL = sb + OFF_FL + r * 512;
    const uint32_t bRow = (uint32_t)((n0 + (lane & 7)) * 512 + jb * 4096);
    const uint32_t bH = sb + OFF_WH + bRow;
    const uint32_t bL = sb + OFF_WL + bRow;
#pragma unroll 4
    for (int kt = 0; kt < 16; kt++) {
        uint32_t aoff = (uint32_t)(((2 * kt + kpa) ^ rx) << 4);
        uint32_t boff = (uint32_t)(((2 * kt + kpb) ^ rx) << 4);
        uint32_t ah[4], al[4];
        ldmx4(ah, aH + aoff);
        ldmx4(al, aL + aoff);
#pragma unroll
        for (int jp = 0; jp < 4; jp++) {
            uint32_t bh[4], bl[4];
            ldmx4(bh, bH + jp * 8192 + boff);
            ldmx4(bl, bL + jp * 8192 + boff);
            mma16816(C  + 8 * jp,     ah, bh);
            mma16816(Cw + 8 * jp,     al, bh);
            mma16816(Cw + 8 * jp,     ah, bl);
            mma16816(C  + 8 * jp + 4, ah, bh + 2);
            mma16816(Cw + 8 * jp + 4, al, bh + 2);
            mma16816(Cw + 8 * jp + 4, ah, bl + 2);
        }
    }
#pragma unroll
    for (int i = 0; i < 32; i++) C[i] = fmaf(Cw[i], LO_INV, C[i]);
}

// ======================= kernel ============================================
__global__ void __launch_bounds__(NTHREADS, 1)
phase_kernel(const float* __restrict__ x, const float* __restrict__ e_w,
             const float* __restrict__ e_b, const float* __restrict__ d_w,
             const float* __restrict__ d_b, const float* __restrict__ r_w,
             const float* __restrict__ r_b, float* __restrict__ outbuf) {
    extern __shared__ char sm[];
    float* smf = (float*)sm;
    const int tid  = threadIdx.x;
    const int lane = tid & 31;
    const int warp = tid >> 5;
    const int mt = warp >> 1, nh = warp & 1;     // m-tile (0..3), n-half (0..1)
    const int Rbase = mt * 16, n0 = nh * 64;
    const int g  = lane >> 2;
    const int c2 = (lane & 3) * 2;
    const int r0 = Rbase + g;                    // local row (thread also owns r0+8)
    const int grow0 = blockIdx.x * MROWS + r0;
    const uint32_t sb = smem_u32(sm);

    // ---- stage small arrays ----
    if (tid < 128) {
        smf[OFF_EW / 4 + tid] = e_w[tid];
        smf[OFF_EB / 4 + tid] = e_b[tid];
        smf[OFF_DB / 4 + tid] = d_b[tid];
        smf[OFF_RW / 4 + tid]       = r_w[tid];
        smf[OFF_RW / 4 + 128 + tid] = r_w[128 + tid];
        smf[OFF_RW / 4 + 256 + tid] = r_w[256 + tid];
    }
    if (tid < MROWS) smf[OFF_OUT / 4 + tid] = 0.f;
    if (tid == 0) smf[OFF_RB / 4] = r_b[0];

    stage_w(sm, d_w, 256, tid);                  // Wx = d_w[:, 256:512] (hi+lo)
    __syncthreads();

    const float x0 = x[grow0];
    const float x1 = x[grow0 + 8];

    // ---- xp feats: cos/sin(x*e_w + e_b) for this thread's (rows, cols) ----
#pragma unroll
    for (int j = 0; j < 8; j++) {
        int cj = n0 + 8 * j + c2;
        float w0 = smf[OFF_EW / 4 + cj], w1 = smf[OFF_EW / 4 + cj + 1];
        float b0 = smf[OFF_EB / 4 + cj], b1 = smf[OFF_EB / 4 + cj + 1];
        float p00 = fmaf(x0, w0, b0), p01 = fmaf(x0, w1, b1);
        float p10 = fmaf(x1, w0, b0), p11 = fmaf(x1, w1, b1);
        float s00, c00, s01, c01, s10, c10, s11, c11;
        __sincosf(p00, &s00, &c00); __sincosf(p01, &s01, &c01);
        __sincosf(p10, &s10, &c10); __sincosf(p11, &s11, &c11);
        emit_feats(sm, r0,     cj, c00, c01, s00, s01);
        emit_feats(sm, r0 + 8, cj, c10, c11, s10, s11);
    }
    __syncthreads();

    float C[32];
#pragma unroll
    for (int i = 0; i < 32; i++) C[i] = 0.f;

    gemm3(C, sb, lane, Rbase, n0);               // C = X = xp_feats @ Wx^T
    __syncthreads();                             // all reads done before restage

    // xdb = X + d_b (registers, same fragment layout as C)
    float xdb[32];
#pragma unroll
    for (int j = 0; j < 8; j++) {
        int cj = n0 + 8 * j + c2;
        float d0 = smf[OFF_DB / 4 + cj], d1 = smf[OFF_DB / 4 + cj + 1];
        xdb[4 * j + 0] = C[4 * j + 0] + d0;
        xdb[4 * j + 1] = C[4 * j + 1] + d1;
        xdb[4 * j + 2] = C[4 * j + 2] + d0;
        xdb[4 * j + 3] = C[4 * j + 3] + d1;
    }

    stage_w(sm, d_w, 0, tid);                    // Wcs = d_w[:, 0:256] (hi+lo)
    // feats for ph_0 = 0: cos = 1, sin = 0 (exact, lo = 0)
#pragma unroll
    for (int j = 0; j < 8; j++) {
        int cj = n0 + 8 * j + c2;
        emit_feats(sm, r0,     cj, 1.f, 1.f, 0.f, 0.f);
        emit_feats(sm, r0 + 8, cj, 1.f, 1.f, 0.f, 0.f);
    }

    float* hst = outbuf + NROWS;                 // Hstack [12, B, 128]
    float racc0 = 0.f, racc1 = 0.f;

    // ---- 12-step recurrence.  ph_t = C + (t-1)*xdb + d_b ----
#pragma unroll 1
    for (int t = 1; t <= NSTEPS; t++) {
        __syncthreads();                         // feats visible to all warps
        gemm3(C, sb, lane, Rbase, n0);           // C += feats @ Wcs^T
        __syncthreads();                         // reads done before overwrite
        const float tm1 = (float)(t - 1);
        float* h0 = hst + (size_t)(t - 1) * HS_STRIDE + (size_t)grow0 * HD;
        float* h1 = h0 + 8 * HD;
#pragma unroll
        for (int j = 0; j < 8; j++) {
            int cj = n0 + 8 * j + c2;
            float d0 = smf[OFF_DB / 4 + cj], d1 = smf[OFF_DB / 4 + cj + 1];
            float p0 = fmaf(tm1, xdb[4 * j + 0], C[4 * j + 0] + d0);
            float p1 = fmaf(tm1, xdb[4 * j + 1], C[4 * j + 1] + d1);
            float p2 = fmaf(tm1, xdb[4 * j + 2], C[4 * j + 2] + d0);
            float p3 = fmaf(tm1, xdb[4 * j + 3], C[4 * j + 3] + d1);
            __stcs((float2*)(h0 + cj), make_float2(p0, p1));
            __stcs((float2*)(h1 + cj), make_float2(p2, p3));
            float s0, cv0, s1, cv1, s2, cv2, s3, cv3;
            __sincosf(p0, &s0, &cv0); __sincosf(p1, &s1, &cv1);
            __sincosf(p2, &s2, &cv2); __sincosf(p3, &s3, &cv3);
            if (t < NSTEPS) {
                emit_feats(sm, r0,     cj, cv0, cv1, s0, s1);
                emit_feats(sm, r0 + 8, cj, cv2, cv3, s2, s3);
            } else {
                // readout: cos*rw0 + sin*rw1 + ph*rw2
                float w0 = smf[OFF_RW / 4 + cj],       w1 = smf[OFF_RW / 4 + cj + 1];
                float v0 = smf[OFF_RW / 4 + 128 + cj], v1 = smf[OFF_RW / 4 + 128 + cj + 1];
                float u0 = smf[OFF_RW / 4 + 256 + cj], u1 = smf[OFF_RW / 4 + 256 + cj + 1];
                racc0 = fmaf(cv0, w0, racc0); racc0 = fmaf(s0, v0, racc0); racc0 = fmaf(p0, u0, racc0);
                racc0 = fmaf(cv1, w1, racc0); racc0 = fmaf(s1, v1, racc0); racc0 = fmaf(p1, u1, racc0);
                racc1 = fmaf(cv2, w0, racc1); racc1 = fmaf(s2, v0, racc1); racc1 = fmaf(p2, u0, racc1);
                racc1 = fmaf(cv3, w1, racc1); racc1 = fmaf(s3, v1, racc1); racc1 = fmaf(p3, u1, racc1);
            }
        }
    }

    // ---- reduce readout across quad lanes, then across the 2 n-half warps ----
    racc0 += __shfl_xor_sync(0xffffffffu, racc0, 1);
    racc0 += __shfl_xor_sync(0xffffffffu, racc0, 2);
    racc1 += __shfl_xor_sync(0xffffffffu, racc1, 1);
    racc1 += __shfl_xor_sync(0xffffffffu, racc1, 2);
    if ((lane & 3) == 0) {
        atomicAdd(&smf[OFF_OUT / 4 + r0], racc0);
        atomicAdd(&smf[OFF_OUT / 4 + r0 + 8], racc1);
    }
    __syncthreads();
    if (tid < MROWS)
        outbuf[blockIdx.x * MROWS + tid] = smf[OFF_OUT / 4 + tid] + smf[OFF_RB / 4];
}

extern "C" void kernel_launch(void* const* d_in, const int* in_sizes, int n_in,
                              void* d_out, int out_size) {
    const float* x   = (const float*)d_in[0];
    const float* e_w = (const float*)d_in[1];
    const float* e_b = (const float*)d_in[2];
    const float* d_w = (const float*)d_in[3];
    const float* d_b = (const float*)d_in[4];
    const float* r_w = (const float*)d_in[5];
    const float* r_b = (const float*)d_in[6];
    float* out = (float*)d_out;

    cudaFuncSetAttribute(phase_kernel,
                         cudaFuncAttributeMaxDynamicSharedMemorySize, SMEM_TOTAL);
    phase_kernel<<<NBLK, NTHREADS, SMEM_TOTAL>>>(x, e_w, e_b, d_w, d_b, r_w, r_b, out);
}

// round 7
// speedup vs baseline: 1.0628x; 1.0628x over previous
#include <cuda_runtime.h>
#include <cuda_fp16.h>
#include <cstdint>

#define NROWS   131072
#define HD      128
#define NSTEPS  12
#define MROWS   64
#define NBLK    (NROWS / MROWS)
#define NTHREADS 256
#define HS_STRIDE ((size_t)NROWS * HD)
#define LO_SCALE   1024.0f
#define LO_INV     (1.0f / 1024.0f)

// ---------------- SMEM layout (byte offsets) -------------------------------
// Big tiles: rows x 512 bytes (256 fp16), 16B-chunk swizzle: chunk ^= (row&7)
#define OFF_WH   0        // W hi fp16: 128(n) x 256(k)     64 KB
#define OFF_WL   65536    // W lo*1024 fp16                 64 KB
#define OFF_FH   131072   // feats hi fp16: 64(m) x 256(k)  32 KB
#define OFF_FL   163840   // feats lo*1024 fp16             32 KB
#define OFF_EW   196608
#define OFF_EB   197120
#define OFF_DB   197632
#define OFF_RW   198144   // 3*128 floats
#define OFF_OUT  199680   // 64 floats
#define OFF_RB   199936
#define OFF_K1   200192   // 128 floats: rowsum of Wcs cos-half (exact fp32)
#define SMEM_TOTAL 200704

// ======================= low-level helpers =================================
static __device__ __forceinline__ uint32_t smem_u32(const void* p) {
    uint32_t a;
    asm("{ .reg .u64 t; cvta.to.shared.u64 t, %1; cvt.u32.u64 %0, t; }" : "=r"(a) : "l"(p));
    return a;
}
static __device__ __forceinline__ void ldmx4(uint32_t* a, uint32_t addr) {
    asm volatile("ldmatrix.sync.aligned.m8n8.x4.shared.b16 {%0,%1,%2,%3}, [%4];"
                 : "=r"(a[0]), "=r"(a[1]), "=r"(a[2]), "=r"(a[3]) : "r"(addr));
}
static __device__ __forceinline__ void mma16816(float* c, const uint32_t* a, const uint32_t* b) {
    asm volatile("mma.sync.aligned.m16n8k16.row.col.f32.f16.f16.f32 "
                 "{%0,%1,%2,%3}, {%4,%5,%6,%7}, {%8,%9}, {%0,%1,%2,%3};"
                 : "+f"(c[0]), "+f"(c[1]), "+f"(c[2]), "+f"(c[3])
                 : "r"(a[0]), "r"(a[1]), "r"(a[2]), "r"(a[3]), "r"(b[0]), "r"(b[1]));
}

// pair-scoped named barrier: the 64 threads of warp-pair mt
#define PAIR_BAR(id) asm volatile("bar.sync %0, 64;" :: "r"(id) : "memory")

// hi/lo fp16 split of a pair; lo scaled by LO_SCALE (keeps lo in fp16 normal range)
static __device__ __forceinline__ void split2(float a, float b, uint32_t& hi, uint32_t& lo) {
    __half ha = __float2half_rn(a), hb = __float2half_rn(b);
    float ra = (a - __half2float(ha)) * LO_SCALE;
    float rb = (b - __half2float(hb)) * LO_SCALE;
    hi = (uint32_t)__half_as_ushort(ha) | ((uint32_t)__half_as_ushort(hb) << 16);
    lo = (uint32_t)__half_as_ushort(__float2half_rn(ra)) |
         ((uint32_t)__half_as_ushort(__float2half_rn(rb)) << 16);
}

// 4B store into a swizzled 512B-row tile
static __device__ __forceinline__ void st4sw(char* sm, int off, int r, int cbyte, uint32_t v) {
    uint32_t chunk = ((uint32_t)(cbyte >> 4)) ^ (uint32_t)(r & 7);
    *(uint32_t*)(sm + off + r * 512 + (chunk << 4) + (cbyte & 15)) = v;
}

// Write cos/sin (hi + scaled lo) for row r, columns cj, cj+1.
// cos -> k = cj (byte 2*cj), sin -> k = 128+cj (byte 256+2*cj)
static __device__ __forceinline__ void emit_feats(char* sm, int r, int cj,
                                                  float c0, float c1, float s0, float s1) {
    uint32_t chi, clo, shi, slo;
    split2(c0, c1, chi, clo);
    split2(s0, s1, shi, slo);
    st4sw(sm, OFF_FH, r, 2 * cj, chi);
    st4sw(sm, OFF_FH, r, 256 + 2 * cj, shi);
    st4sw(sm, OFF_FL, r, 2 * cj, clo);
    st4sw(sm, OFF_FL, r, 256 + 2 * cj, slo);
}

// Stage 128x256 fp32 weight block (d_w cols [colbase, colbase+256)) as fp16
// hi + scaled-lo into OFF_WH/OFF_WL with the swizzled layout. 256 threads:
// thread = (row r = tid>>1, k-half = tid&1).
static __device__ __forceinline__ void stage_w(char* sm, const float* __restrict__ dw,
                                               int colbase, int tid) {
    int r = tid >> 1, half = tid & 1;
    const float4* src = (const float4*)(dw + (size_t)r * 512 + colbase + 128 * half);
    int rx = r & 7;
    char* dh = sm + OFF_WH + r * 512;
    char* dl = sm + OFF_WL + r * 512;
#pragma unroll
    for (int i = 0; i < 16; i++) {
        float4 v0 = src[2 * i];
        float4 v1 = src[2 * i + 1];
        uint4 h, l;
        split2(v0.x, v0.y, h.x, l.x);
        split2(v0.z, v0.w, h.y, l.y);
        split2(v1.x, v1.y, h.z, l.z);
        split2(v1.z, v1.w, h.w, l.w);
        uint32_t chunk = (uint32_t)((half * 16 + i) ^ rx);
        *(uint4*)(dh + (chunk << 4)) = h;
        *(uint4*)(dl + (chunk << 4)) = l;
    }
}

// 3-pass split GEMM: C += Ah@Wh^T + (Al@Wh^T + Ah@Wl^T)/1024. K=256, tile 16x64.
static __device__ __forceinline__ void gemm3(float* C, uint32_t sb, int lane,
                                             int Rbase, int n0) {
    float Cw[32];
#pragma unroll
    for (int i = 0; i < 32; i++) Cw[i] = 0.f;
    const int r   = Rbase + (lane & 7) + ((lane >> 3) & 1) * 8;
    const int rx  = lane & 7;
    const int kpa = lane >> 4;                   // A: k-chunk parity per lane group
    const int kpb = (lane >> 3) & 1;             // B: k-chunk parity
    const int jb  = (lane >> 4) & 1;             // B: j within the j-pair
    const uint32_t aH = sb + OFF_FH + r * 512;
    const uint32_t aL = sb + OFF_FL + r * 512;
    const uint32_t bRow = (uint32_t)((n0 + (lane & 7)) * 512 + jb * 4096);
    const uint32_t bH = sb + OFF_WH + bRow;
    const uint32_t bL = sb + OFF_WL + bRow;
#pragma unroll 4
    for (int kt = 0; kt < 16; kt++) {
        uint32_t aoff = (uint32_t)(((2 * kt + kpa) ^ rx) << 4);
        uint32_t boff = (uint32_t)(((2 * kt + kpb) ^ rx) << 4);
        uint32_t ah[4], al[4];
        ldmx4(ah, aH + aoff);
        ldmx4(al, aL + aoff);
#pragma unroll
        for (int jp = 0; jp < 4; jp++) {
            uint32_t bh[4], bl[4];
            ldmx4(bh, bH + jp * 8192 + boff);
            ldmx4(bl, bL + jp * 8192 + boff);
            mma16816(C  + 8 * jp,     ah, bh);
            mma16816(Cw + 8 * jp,     al, bh);
            mma16816(Cw + 8 * jp,     ah, bl);
            mma16816(C  + 8 * jp + 4, ah, bh + 2);
            mma16816(Cw + 8 * jp + 4, al, bh + 2);
            mma16816(Cw + 8 * jp + 4, ah, bl + 2);
        }
    }
#pragma unroll
    for (int i = 0; i < 32; i++) C[i] = fmaf(Cw[i], LO_INV, C[i]);
}

// ======================= kernel ============================================
__global__ void __launch_bounds__(NTHREADS, 1)
phase_kernel(const float* __restrict__ x, const float* __restrict__ e_w,
             const float* __restrict__ e_b, const float* __restrict__ d_w,
             const float* __restrict__ d_b, const float* __restrict__ r_w,
             const float* __restrict__ r_b, float* __restrict__ outbuf) {
    extern __shared__ char sm[];
    float* smf = (float*)sm;
    const int tid  = threadIdx.x;
    const int lane = tid & 31;
    const int warp = tid >> 5;
    const int mt = warp >> 1, nh = warp & 1;     // m-tile (0..3), n-half (0..1)
    const int Rbase = mt * 16, n0 = nh * 64;
    const int pbar = 1 + mt;                     // named barrier id for this pair
    const int g  = lane >> 2;
    const int c2 = (lane & 3) * 2;
    const int r0 = Rbase + g;                    // local row (thread also owns r0+8)
    const int grow0 = blockIdx.x * MROWS + r0;
    const uint32_t sb = smem_u32(sm);

    // ---- stage small arrays; compute exact K1 = rowsum(Wcs cos-half) ----
    if (tid < 128) {
        smf[OFF_EW / 4 + tid] = e_w[tid];
        smf[OFF_EB / 4 + tid] = e_b[tid];
        smf[OFF_DB / 4 + tid] = d_b[tid];
        smf[OFF_RW / 4 + tid]       = r_w[tid];
        smf[OFF_RW / 4 + 128 + tid] = r_w[128 + tid];
        smf[OFF_RW / 4 + 256 + tid] = r_w[256 + tid];
        const float4* wr = (const float4*)(d_w + (size_t)tid * 512);
        float s = 0.f;
#pragma unroll 8
        for (int i = 0; i < 32; i++) {
            float4 v = wr[i];
            s += v.x + v.y + v.z + v.w;
        }
        smf[OFF_K1 / 4 + tid] = s;
    }
    if (tid < MROWS) smf[OFF_OUT / 4 + tid] = 0.f;
    if (tid == 0) smf[OFF_RB / 4] = r_b[0];

    stage_w(sm, d_w, 256, tid);                  // Wx = d_w[:, 256:512] (hi+lo)
    __syncthreads();

    const float x0 = x[grow0];
    const float x1 = x[grow0 + 8];

    // ---- xp feats: cos/sin(x*e_w + e_b) for this thread's (rows, cols) ----
#pragma unroll
    for (int j = 0; j < 8; j++) {
        int cj = n0 + 8 * j + c2;
        float w0 = smf[OFF_EW / 4 + cj], w1 = smf[OFF_EW / 4 + cj + 1];
        float b0 = smf[OFF_EB / 4 + cj], b1 = smf[OFF_EB / 4 + cj + 1];
        float p00 = fmaf(x0, w0, b0), p01 = fmaf(x0, w1, b1);
        float p10 = fmaf(x1, w0, b0), p11 = fmaf(x1, w1, b1);
        float s00, c00, s01, c01, s10, c10, s11, c11;
        __sincosf(p00, &s00, &c00); __sincosf(p01, &s01, &c01);
        __sincosf(p10, &s10, &c10); __sincosf(p11, &s11, &c11);
        emit_feats(sm, r0,     cj, c00, c01, s00, s01);
        emit_feats(sm, r0 + 8, cj, c10, c11, s10, s11);
    }
    __syncthreads();

    float C[32];
#pragma unroll
    for (int i = 0; i < 32; i++) C[i] = 0.f;

    gemm3(C, sb, lane, Rbase, n0);               // C = X0 = xp_feats @ Wx^T
    __syncthreads();                             // all reads of Wx/feats done

    // xdb = X0 + d_b (registers); fold exact-K1 (t=1 GEMM contribution) into C
    float xdb[32];
#pragma unroll
    for (int j = 0; j < 8; j++) {
        int cj = n0 + 8 * j + c2;
        float d0 = smf[OFF_DB / 4 + cj], d1 = smf[OFF_DB / 4 + cj + 1];
        float k0 = smf[OFF_K1 / 4 + cj], k1 = smf[OFF_K1 / 4 + cj + 1];
        xdb[4 * j + 0] = C[4 * j + 0] + d0;
        xdb[4 * j + 1] = C[4 * j + 1] + d1;
        xdb[4 * j + 2] = C[4 * j + 2] + d0;
        xdb[4 * j + 3] = C[4 * j + 3] + d1;
        C[4 * j + 0] += k0;
        C[4 * j + 1] += k1;
        C[4 * j + 2] += k0;
        C[4 * j + 3] += k1;
    }

    stage_w(sm, d_w, 0, tid);                    // Wcs = d_w[:, 0:256] (hi+lo)
    __syncthreads();                             // Wcs visible; feats tile free

    float* hst = outbuf + NROWS;                 // Hstack [12, B, 128]
    float racc0 = 0.f, racc1 = 0.f;

    // ---- recurrence.  At loop top: C = C_t, ph_t = C + (t-1)*xdb + d_b.
    //      Pair-scoped barriers only: the 4 m-tile pairs skew freely, so one
    //      pair's MUFU/emit overlaps another pair's MMA/LDSM. ----
#pragma unroll 1
    for (int t = 1; t <= NSTEPS; t++) {
        const float tm1 = (float)(t - 1);
        float* h0 = hst + (size_t)(t - 1) * HS_STRIDE + (size_t)grow0 * HD;
        float* h1 = h0 + 8 * HD;
#pragma unroll
        for (int j = 0; j < 8; j++) {
            int cj = n0 + 8 * j + c2;
            float d0 = smf[OFF_DB / 4 + cj], d1 = smf[OFF_DB / 4 + cj + 1];
            float p0 = fmaf(tm1, xdb[4 * j + 0], C[4 * j + 0] + d0);
            float p1 = fmaf(tm1, xdb[4 * j + 1], C[4 * j + 1] + d1);
            float p2 = fmaf(tm1, xdb[4 * j + 2], C[4 * j + 2] + d0);
            float p3 = fmaf(tm1, xdb[4 * j + 3], C[4 * j + 3] + d1);
            __stcs((float2*)(h0 + cj), make_float2(p0, p1));
            __stcs((float2*)(h1 + cj), make_float2(p2, p3));
            float s0, cv0, s1, cv1, s2, cv2, s3, cv3;
            __sincosf(p0, &s0, &cv0); __sincosf(p1, &s1, &cv1);
            __sincosf(p2, &s2, &cv2); __sincosf(p3, &s3, &cv3);
            if (t < NSTEPS) {
                emit_feats(sm, r0,     cj, cv0, cv1, s0, s1);
                emit_feats(sm, r0 + 8, cj, cv2, cv3, s2, s3);
            } else {
                // readout: cos*rw0 + sin*rw1 + ph*rw2
                float w0 = smf[OFF_RW / 4 + cj],       w1 = smf[OFF_RW / 4 + cj + 1];
                float v0 = smf[OFF_RW / 4 + 128 + cj], v1 = smf[OFF_RW / 4 + 128 + cj + 1];
                float u0 = smf[OFF_RW / 4 + 256 + cj], u1 = smf[OFF_RW / 4 + 256 + cj + 1];
                racc0 = fmaf(cv0, w0, racc0); racc0 = fmaf(s0, v0, racc0); racc0 = fmaf(p0, u0, racc0);
                racc0 = fmaf(cv1, w1, racc0); racc0 = fmaf(s1, v1, racc0); racc0 = fmaf(p1, u1, racc0);
                racc1 = fmaf(cv2, w0, racc1); racc1 = fmaf(s2, v0, racc1); racc1 = fmaf(p2, u0, racc1);
                racc1 = fmaf(cv3, w1, racc1); racc1 = fmaf(s3, v1, racc1); racc1 = fmaf(p3, u1, racc1);
            }
        }
        if (t < NSTEPS) {
            PAIR_BAR(pbar);                      // pair's feats(ph_t) written
            gemm3(C, sb, lane, Rbase, n0);       // C += feats @ Wcs^T
            PAIR_BAR(pbar);                      // pair done reading feats
        }
    }

    // ---- reduce readout across quad lanes, then across the 2 n-half warps ----
    racc0 += __shfl_xor_sync(0xffffffffu, racc0, 1);
    racc0 += __shfl_xor_sync(0xffffffffu, racc0, 2);
    racc1 += __shfl_xor_sync(0xffffffffu, racc1, 1);
    racc1 += __shfl_xor_sync(0xffffffffu, racc1, 2);
    if ((lane & 3) == 0) {
        atomicAdd(&smf[OFF_OUT / 4 + r0], racc0);
        atomicAdd(&smf[OFF_OUT / 4 + r0 + 8], racc1);
    }
    __syncthreads();
    if (tid < MROWS)
        outbuf[blockIdx.x * MROWS + tid] = smf[OFF_OUT / 4 + tid] + smf[OFF_RB / 4];
}

extern "C" void kernel_launch(void* const* d_in, const int* in_sizes, int n_in,
                              void* d_out, int out_size) {
    const float* x   = (const float*)d_in[0];
    const float* e_w = (const float*)d_in[1];
    const float* e_b = (const float*)d_in[2];
    const float* d_w = (const float*)d_in[3];
    const float* d_b = (const float*)d_in[4];
    const float* r_w = (const float*)d_in[5];
    const float* r_b = (const float*)d_in[6];
    float* out = (float*)d_out;

    cudaFuncSetAttribute(phase_kernel,
                         cudaFuncAttributeMaxDynamicSharedMemorySize, SMEM_TOTAL);
    phase_kernel<<<NBLK, NTHREADS, SMEM_TOTAL>>>(x, e_w, e_b, d_w, d_b, r_w, r_b, out);
}

// round 9
// speedup vs baseline: 1.1019x; 1.0368x over previous
#include <cuda_runtime.h>
#include <cuda_fp16.h>
#include <cstdint>

#define NROWS   131072
#define HD      128
#define NSTEPS  12
#define MROWS   64
#define NBLK    (NROWS / MROWS)
#define NTHREADS 512
#define HS_STRIDE ((size_t)NROWS * HD)
#define LO_SCALE   1024.0f
#define LO_INV     (1.0f / 1024.0f)

// ---------------- SMEM layout (byte offsets) -------------------------------
// Big tiles: rows x 512 bytes (256 fp16), 16B-chunk swizzle: chunk ^= (row&7)
#define OFF_WH   0        // W hi fp16: 128(n) x 256(k)     64 KB
#define OFF_WL   65536    // W lo*1024 fp16                 64 KB
#define OFF_FH   131072   // feats hi fp16: 64(m) x 256(k)  32 KB
#define OFF_FL   163840   // feats lo*1024 fp16             32 KB
#define OFF_EW   196608
#define OFF_EB   197120
#define OFF_DB   197632
#define OFF_RW   198144   // 3*128 floats
#define OFF_OUT  199680   // 64 floats
#define OFF_RB   199936
#define OFF_K1   200192   // 128 floats: rowsum of Wcs cos-half (exact fp32)
#define SMEM_TOTAL 200704

// ======================= low-level helpers =================================
static __device__ __forceinline__ uint32_t smem_u32(const void* p) {
    uint32_t a;
    asm("{ .reg .u64 t; cvta.to.shared.u64 t, %1; cvt.u32.u64 %0, t; }" : "=r"(a) : "l"(p));
    return a;
}
static __device__ __forceinline__ void ldmx4(uint32_t* a, uint32_t addr) {
    asm volatile("ldmatrix.sync.aligned.m8n8.x4.shared.b16 {%0,%1,%2,%3}, [%4];"
                 : "=r"(a[0]), "=r"(a[1]), "=r"(a[2]), "=r"(a[3]) : "r"(addr));
}
static __device__ __forceinline__ void mma16816(float* c, const uint32_t* a, const uint32_t* b) {
    asm volatile("mma.sync.aligned.m16n8k16.row.col.f32.f16.f16.f32 "
                 "{%0,%1,%2,%3}, {%4,%5,%6,%7}, {%8,%9}, {%0,%1,%2,%3};"
                 : "+f"(c[0]), "+f"(c[1]), "+f"(c[2]), "+f"(c[3])
                 : "r"(a[0]), "r"(a[1]), "r"(a[2]), "r"(a[3]), "r"(b[0]), "r"(b[1]));
}

// mt-group barrier: the 128 threads (4 warps) of m-tile group mt
#define GROUP_BAR(id) asm volatile("bar.sync %0, 128;" :: "r"(id) : "memory")

// hi/lo fp16 split of a pair; lo scaled by LO_SCALE (keeps lo in fp16 normal range)
static __device__ __forceinline__ void split2(float a, float b, uint32_t& hi, uint32_t& lo) {
    __half ha = __float2half_rn(a), hb = __float2half_rn(b);
    float ra = (a - __half2float(ha)) * LO_SCALE;
    float rb = (b - __half2float(hb)) * LO_SCALE;
    hi = (uint32_t)__half_as_ushort(ha) | ((uint32_t)__half_as_ushort(hb) << 16);
    lo = (uint32_t)__half_as_ushort(__float2half_rn(ra)) |
         ((uint32_t)__half_as_ushort(__float2half_rn(rb)) << 16);
}

// 4B store into a swizzled 512B-row tile
static __device__ __forceinline__ void st4sw(char* sm, int off, int r, int cbyte, uint32_t v) {
    uint32_t chunk = ((uint32_t)(cbyte >> 4)) ^ (uint32_t)(r & 7);
    *(uint32_t*)(sm + off + r * 512 + (chunk << 4) + (cbyte & 15)) = v;
}

// Write cos/sin (hi + scaled lo) for row r, columns cj, cj+1.
// cos -> k = cj (byte 2*cj), sin -> k = 128+cj (byte 256+2*cj)
static __device__ __forceinline__ void emit_feats(char* sm, int r, int cj,
                                                  float c0, float c1, float s0, float s1) {
    uint32_t chi, clo, shi, slo;
    split2(c0, c1, chi, clo);
    split2(s0, s1, shi, slo);
    st4sw(sm, OFF_FH, r, 2 * cj, chi);
    st4sw(sm, OFF_FH, r, 256 + 2 * cj, shi);
    st4sw(sm, OFF_FL, r, 2 * cj, clo);
    st4sw(sm, OFF_FL, r, 256 + 2 * cj, slo);
}

// Stage 128x256 fp32 weight block (d_w cols [colbase, colbase+256)) as fp16
// hi + scaled-lo into OFF_WH/OFF_WL with the swizzled layout. 512 threads:
// thread = (row r = tid>>2, col-quarter q = tid&3).
static __device__ __forceinline__ void stage_w(char* sm, const float* __restrict__ dw,
                                               int colbase, int tid) {
    int r = tid >> 2, q = tid & 3;
    const float4* src = (const float4*)(dw + (size_t)r * 512 + colbase + 64 * q);
    int rx = r & 7;
    char* dh = sm + OFF_WH + r * 512;
    char* dl = sm + OFF_WL + r * 512;
#pragma unroll
    for (int i = 0; i < 8; i++) {
        float4 v0 = src[2 * i];
        float4 v1 = src[2 * i + 1];
        uint4 h, l;
        split2(v0.x, v0.y, h.x, l.x);
        split2(v0.z, v0.w, h.y, l.y);
        split2(v1.x, v1.y, h.z, l.z);
        split2(v1.z, v1.w, h.w, l.w);
        uint32_t chunk = (uint32_t)((q * 8 + i) ^ rx);
        *(uint4*)(dh + (chunk << 4)) = h;
        *(uint4*)(dl + (chunk << 4)) = l;
    }
}

// 3-pass split GEMM: C += Ah@Wh^T + (Al@Wh^T + Ah@Wl^T)/1024. K=256, tile 16x32.
static __device__ __forceinline__ void gemm3(float* C, uint32_t sb, int lane,
                                             int Rbase, int n0) {
    float Cw[16];
#pragma unroll
    for (int i = 0; i < 16; i++) Cw[i] = 0.f;
    const int r   = Rbase + (lane & 7) + ((lane >> 3) & 1) * 8;
    const int rx  = lane & 7;
    const int kpa = lane >> 4;                   // A: k-chunk parity per lane group
    const int kpb = (lane >> 3) & 1;             // B: k-chunk parity
    const int jb  = (lane >> 4) & 1;             // B: n-octet within the 16-row group
    const uint32_t aH = sb + OFF_FH + r * 512;
    const uint32_t aL = sb + OFF_FL + r * 512;
    const uint32_t bRow = (uint32_t)((n0 + (lane & 7)) * 512 + jb * 4096);
    const uint32_t bH = sb + OFF_WH + bRow;
    const uint32_t bL = sb + OFF_WL + bRow;
#pragma unroll 4
    for (int kt = 0; kt < 16; kt++) {
        uint32_t aoff = (uint32_t)(((2 * kt + kpa) ^ rx) << 4);
        uint32_t boff = (uint32_t)(((2 * kt + kpb) ^ rx) << 4);
        uint32_t ah[4], al[4];
        ldmx4(ah, aH + aoff);
        ldmx4(al, aL + aoff);
#pragma unroll
        for (int jp = 0; jp < 2; jp++) {
            uint32_t bh[4], bl[4];
            ldmx4(bh, bH + jp * 8192 + boff);
            ldmx4(bl, bL + jp * 8192 + boff);
            mma16816(C  + 8 * jp,     ah, bh);
            mma16816(Cw + 8 * jp,     al, bh);
            mma16816(Cw + 8 * jp,     ah, bl);
            mma16816(C  + 8 * jp + 4, ah, bh + 2);
            mma16816(Cw + 8 * jp + 4, al, bh + 2);
            mma16816(Cw + 8 * jp + 4, ah, bl + 2);
        }
    }
#pragma unroll
    for (int i = 0; i < 16; i++) C[i] = fmaf(Cw[i], LO_INV, C[i]);
}

// ======================= kernel ============================================
__global__ void __launch_bounds__(NTHREADS, 1)
phase_kernel(const float* __restrict__ x, const float* __restrict__ e_w,
             const float* __restrict__ e_b, const float* __restrict__ d_w,
             const float* __restrict__ d_b, const float* __restrict__ r_w,
             const float* __restrict__ r_b, float* __restrict__ outbuf) {
    extern __shared__ char sm[];
    float* smf = (float*)sm;
    const int tid  = threadIdx.x;
    const int lane = tid & 31;
    const int warp = tid >> 5;
    const int mt = warp >> 2, nq = warp & 3;     // m-tile (0..3), n-quarter (0..3)
    const int Rbase = mt * 16, n0 = nq * 32;
    const int gbar = 1 + mt;                     // named barrier id for this group
    const int g  = lane >> 2;
    const int c2 = (lane & 3) * 2;
    const int r0 = Rbase + g;                    // local row (thread also owns r0+8)
    const int grow0 = blockIdx.x * MROWS + r0;
    const uint32_t sb = smem_u32(sm);

    // ---- stage small arrays; compute exact K1 = rowsum(Wcs cos-half) ----
    if (tid < 128) {
        smf[OFF_EW / 4 + tid] = e_w[tid];
        smf[OFF_EB / 4 + tid] = e_b[tid];
        smf[OFF_DB / 4 + tid] = d_b[tid];
        smf[OFF_RW / 4 + tid]       = r_w[tid];
        smf[OFF_RW / 4 + 128 + tid] = r_w[128 + tid];
        smf[OFF_RW / 4 + 256 + tid] = r_w[256 + tid];
        const float4* wr = (const float4*)(d_w + (size_t)tid * 512);
        float s = 0.f;
#pragma unroll 8
        for (int i = 0; i < 32; i++) {
            float4 v = wr[i];
            s += v.x + v.y + v.z + v.w;
        }
        smf[OFF_K1 / 4 + tid] = s;
    }
    if (tid < MROWS) smf[OFF_OUT / 4 + tid] = 0.f;
    if (tid == 0) smf[OFF_RB / 4] = r_b[0];

    stage_w(sm, d_w, 256, tid);                  // Wx = d_w[:, 256:512] (hi+lo)
    __syncthreads();

    const float x0 = x[grow0];
    const float x1 = x[grow0 + 8];

    // ---- xp feats: cos/sin(x*e_w + e_b) for this thread's (rows, cols) ----
#pragma unroll
    for (int j = 0; j < 4; j++) {
        int cj = n0 + 8 * j + c2;
        float w0 = smf[OFF_EW / 4 + cj], w1 = smf[OFF_EW / 4 + cj + 1];
        float b0 = smf[OFF_EB / 4 + cj], b1 = smf[OFF_EB / 4 + cj + 1];
        float p00 = fmaf(x0, w0, b0), p01 = fmaf(x0, w1, b1);
        float p10 = fmaf(x1, w0, b0), p11 = fmaf(x1, w1, b1);
        float s00, c00, s01, c01, s10, c10, s11, c11;
        __sincosf(p00, &s00, &c00); __sincosf(p01, &s01, &c01);
        __sincosf(p10, &s10, &c10); __sincosf(p11, &s11, &c11);
        emit_feats(sm, r0,     cj, c00, c01, s00, s01);
        emit_feats(sm, r0 + 8, cj, c10, c11, s10, s11);
    }
    __syncthreads();

    float C[16];
#pragma unroll
    for (int i = 0; i < 16; i++) C[i] = 0.f;

    gemm3(C, sb, lane, Rbase, n0);               // C = X0 = xp_feats @ Wx^T
    __syncthreads();                             // all reads of Wx/feats done

    // xdb = X0 + d_b (registers); fold exact-K1 (t=1 GEMM contribution) into C
    float xdb[16];
#pragma unroll
    for (int j = 0; j < 4; j++) {
        int cj = n0 + 8 * j + c2;
        float d0 = smf[OFF_DB / 4 + cj], d1 = smf[OFF_DB / 4 + cj + 1];
        float k0 = smf[OFF_K1 / 4 + cj], k1 = smf[OFF_K1 / 4 + cj + 1];
        xdb[4 * j + 0] = C[4 * j + 0] + d0;
        xdb[4 * j + 1] = C[4 * j + 1] + d1;
        xdb[4 * j + 2] = C[4 * j + 2] + d0;
        xdb[4 * j + 3] = C[4 * j + 3] + d1;
        C[4 * j + 0] += k0;
        C[4 * j + 1] += k1;
        C[4 * j + 2] += k0;
        C[4 * j + 3] += k1;
    }

    stage_w(sm, d_w, 0, tid);                    // Wcs = d_w[:, 0:256] (hi+lo)
    __syncthreads();                             // Wcs visible; feats tile free

    float* hst = outbuf + NROWS;                 // Hstack [12, B, 128]
    float racc0 = 0.f, racc1 = 0.f;

    // ---- recurrence.  At loop top: C = C_t, ph_t = C + (t-1)*xdb + d_b.
    //      Group-scoped barriers only: the 4 m-tile groups skew freely; every
    //      SMSP hosts one warp of each group, so skew converts to pipe overlap. ----
#pragma unroll 1
    for (int t = 1; t <= NSTEPS; t++) {
        const float tm1 = (float)(t - 1);
        float* h0 = hst + (size_t)(t - 1) * HS_STRIDE + (size_t)grow0 * HD;
        float* h1 = h0 + 8 * HD;
#pragma unroll
        for (int j = 0; j < 4; j++) {
            int cj = n0 + 8 * j + c2;
            float d0 = smf[OFF_DB / 4 + cj], d1 = smf[OFF_DB / 4 + cj + 1];
            float p0 = fmaf(tm1, xdb[4 * j + 0], C[4 * j + 0] + d0);
            float p1 = fmaf(tm1, xdb[4 * j + 1], C[4 * j + 1] + d1);
            float p2 = fmaf(tm1, xdb[4 * j + 2], C[4 * j + 2] + d0);
            float p3 = fmaf(tm1, xdb[4 * j + 3], C[4 * j + 3] + d1);
            __stcs((float2*)(h0 + cj), make_float2(p0, p1));
            __stcs((float2*)(h1 + cj), make_float2(p2, p3));
            float s0, cv0, s1, cv1, s2, cv2, s3, cv3;
            __sincosf(p0, &s0, &cv0); __sincosf(p1, &s1, &cv1);
            __sincosf(p2, &s2, &cv2); __sincosf(p3, &s3, &cv3);
            if (t < NSTEPS) {
                emit_feats(sm, r0,     cj, cv0, cv1, s0, s1);
                emit_feats(sm, r0 + 8, cj, cv2, cv3, s2, s3);
            } else {
                // readout: cos*rw0 + sin*rw1 + ph*rw2
                float w0 = smf[OFF_RW / 4 + cj],       w1 = smf[OFF_RW / 4 + cj + 1];
                float v0 = smf[OFF_RW / 4 + 128 + cj], v1 = smf[OFF_RW / 4 + 128 + cj + 1];
                float u0 = smf[OFF_RW / 4 + 256 + cj], u1 = smf[OFF_RW / 4 + 256 + cj + 1];
                racc0 = fmaf(cv0, w0, racc0); racc0 = fmaf(s0, v0, racc0); racc0 = fmaf(p0, u0, racc0);
                racc0 = fmaf(cv1, w1, racc0); racc0 = fmaf(s1, v1, racc0); racc0 = fmaf(p1, u1, racc0);
                racc1 = fmaf(cv2, w0, racc1); racc1 = fmaf(s2, v0, racc1); racc1 = fmaf(p2, u0, racc1);
                racc1 = fmaf(cv3, w1, racc1); racc1 = fmaf(s3, v1, racc1); racc1 = fmaf(p3, u1, racc1);
            }
        }
        if (t < NSTEPS) {
            GROUP_BAR(gbar);                     // group's feats(ph_t) written
            gemm3(C, sb, lane, Rbase, n0);       // C += feats @ Wcs^T
            GROUP_BAR(gbar);                     // group done reading feats
        }
    }

    // ---- reduce readout across quad lanes, then across the 4 n-quarter warps ----
    racc0 += __shfl_xor_sync(0xffffffffu, racc0, 1);
    racc0 += __shfl_xor_sync(0xffffffffu, racc0, 2);
    racc1 += __shfl_xor_sync(0xffffffffu, racc1, 1);
    racc1 += __shfl_xor_sync(0xffffffffu, racc1, 2);
    if ((lane & 3) == 0) {
        atomicAdd(&smf[OFF_OUT / 4 + r0], racc0);
        atomicAdd(&smf[OFF_OUT / 4 + r0 + 8], racc1);
    }
    __syncthreads();
    if (tid < MROWS)
        outbuf[blockIdx.x * MROWS + tid] = smf[OFF_OUT / 4 + tid] + smf[OFF_RB / 4];
}

extern "C" void kernel_launch(void* const* d_in, const int* in_sizes, int n_in,
                              void* d_out, int out_size) {
    const float* x   = (const float*)d_in[0];
    const float* e_w = (const float*)d_in[1];
    const float* e_b = (const float*)d_in[2];
    const float* d_w = (const float*)d_in[3];
    const float* d_b = (const float*)d_in[4];
    const float* r_w = (const float*)d_in[5];
    const float* r_b = (const float*)d_in[6];
    float* out = (float*)d_out;

    cudaFuncSetAttribute(phase_kernel,
                         cudaFuncAttributeMaxDynamicSharedMemorySize, SMEM_TOTAL);
    phase_kernel<<<NBLK, NTHREADS, SMEM_TOTAL>>>(x, e_w, e_b, d_w, d_b, r_w, r_b, out);
}

// round 10
// speedup vs baseline: 1.1137x; 1.0107x over previous
#include <cuda_runtime.h>
#include <cuda_fp16.h>
#include <cstdint>

#define NROWS   131072
#define HD      128
#define NSTEPS  12
#define MROWS   64
#define NBLK    (NROWS / MROWS)
#define NTHREADS 256
#define HS_STRIDE ((size_t)NROWS * HD)
#define LO_SCALE   1024.0f
#define LO_INV     (1.0f / 1024.0f)

// ---------------- SMEM layout (byte offsets) -------------------------------
// Big tiles: rows x 512 bytes (256 fp16), 16B-chunk swizzle: chunk ^= (row&7)
#define OFF_WH   0        // W hi fp16: 128(n) x 256(k)     64 KB
#define OFF_WL   65536    // W lo*1024 fp16                 64 KB
#define OFF_FH   131072   // feats hi fp16: 64(m) x 256(k)  32 KB
#define OFF_FL   163840   // feats lo*1024 fp16             32 KB
#define OFF_EW   196608
#define OFF_EB   197120
#define OFF_DB   197632
#define OFF_RW   198144   // 3*128 floats
#define OFF_OUT  199680   // 64 floats
#define OFF_RB   199936
#define OFF_K1   200192   // 128 floats: rowsum of Wcs cos-half (exact fp32)
#define SMEM_TOTAL 200704

// ======================= low-level helpers =================================
static __device__ __forceinline__ uint32_t smem_u32(const void* p) {
    uint32_t a;
    asm("{ .reg .u64 t; cvta.to.shared.u64 t, %1; cvt.u32.u64 %0, t; }" : "=r"(a) : "l"(p));
    return a;
}
static __device__ __forceinline__ void ldmx4(uint32_t* a, uint32_t addr) {
    asm volatile("ldmatrix.sync.aligned.m8n8.x4.shared.b16 {%0,%1,%2,%3}, [%4];"
                 : "=r"(a[0]), "=r"(a[1]), "=r"(a[2]), "=r"(a[3]) : "r"(addr));
}
static __device__ __forceinline__ void mma16816(float* c, const uint32_t* a, const uint32_t* b) {
    asm volatile("mma.sync.aligned.m16n8k16.row.col.f32.f16.f16.f32 "
                 "{%0,%1,%2,%3}, {%4,%5,%6,%7}, {%8,%9}, {%0,%1,%2,%3};"
                 : "+f"(c[0]), "+f"(c[1]), "+f"(c[2]), "+f"(c[3])
                 : "r"(a[0]), "r"(a[1]), "r"(a[2]), "r"(a[3]), "r"(b[0]), "r"(b[1]));
}

// mt-group barrier: the 128 threads (4 warps) of m-tile group mt
#define GROUP_BAR(id) asm volatile("bar.sync %0, 128;" :: "r"(id) : "memory")

// hi/lo fp16 split of a pair; lo scaled by LO_SCALE (keeps lo in fp16 normal range)
static __device__ __forceinline__ void split2(float a, float b, uint32_t& hi, uint32_t& lo) {
    __half ha = __float2half_rn(a), hb = __float2half_rn(b);
    float ra = (a - __half2float(ha)) * LO_SCALE;
    float rb = (b - __half2float(hb)) * LO_SCALE;
    hi = (uint32_t)__half_as_ushort(ha) | ((uint32_t)__half_as_ushort(hb) << 16);
    lo = (uint32_t)__half_as_ushort(__float2half_rn(ra)) |
         ((uint32_t)__half_as_ushort(__float2half_rn(rb)) << 16);
}

// 4B store into a swizzled 512B-row tile
static __device__ __forceinline__ void st4sw(char* sm, int off, int r, int cbyte, uint32_t v) {
    uint32_t chunk = ((uint32_t)(cbyte >> 4)) ^ (uint32_t)(r & 7);
    *(uint32_t*)(sm + off + r * 512 + (chunk << 4) + (cbyte & 15)) = v;
}

// Write cos/sin (hi + scaled lo) for row r, columns cj, cj+1.
// cos -> k = cj (byte 2*cj), sin -> k = 128+cj (byte 256+2*cj)
static __device__ __forceinline__ void emit_feats(char* sm, int r, int cj,
                                                  float c0, float c1, float s0, float s1) {
    uint32_t chi, clo, shi, slo;
    split2(c0, c1, chi, clo);
    split2(s0, s1, shi, slo);
    st4sw(sm, OFF_FH, r, 2 * cj, chi);
    st4sw(sm, OFF_FH, r, 256 + 2 * cj, shi);
    st4sw(sm, OFF_FL, r, 2 * cj, clo);
    st4sw(sm, OFF_FL, r, 256 + 2 * cj, slo);
}

// Stage 128x256 fp32 weight block (d_w cols [colbase, colbase+256)) as fp16
// hi + scaled-lo into OFF_WH/OFF_WL with the swizzled layout. 256 threads:
// thread = (row r = tid>>1, k-half = tid&1).
static __device__ __forceinline__ void stage_w(char* sm, const float* __restrict__ dw,
                                               int colbase, int tid) {
    int r = tid >> 1, half = tid & 1;
    const float4* src = (const float4*)(dw + (size_t)r * 512 + colbase + 128 * half);
    int rx = r & 7;
    char* dh = sm + OFF_WH + r * 512;
    char* dl = sm + OFF_WL + r * 512;
#pragma unroll
    for (int i = 0; i < 16; i++) {
        float4 v0 = src[2 * i];
        float4 v1 = src[2 * i + 1];
        uint4 h, l;
        split2(v0.x, v0.y, h.x, l.x);
        split2(v0.z, v0.w, h.y, l.y);
        split2(v1.x, v1.y, h.z, l.z);
        split2(v1.z, v1.w, h.w, l.w);
        uint32_t chunk = (uint32_t)((half * 16 + i) ^ rx);
        *(uint4*)(dh + (chunk << 4)) = h;
        *(uint4*)(dl + (chunk << 4)) = l;
    }
}

// 3-pass split GEMM: C += Ah@Wh^T + (Al@Wh^T + Ah@Wl^T)/1024. K=256, tile 32x32.
// C layout: C[mi*16 + j*4 + q], mi = m16-tile, j = n8-tile, q = c-frag quad.
static __device__ __forceinline__ void gemm3(float* C, uint32_t sb, int lane,
                                             int Rbase, int n0) {
    float Cw[32];
#pragma unroll
    for (int i = 0; i < 32; i++) Cw[i] = 0.f;
    const int r   = Rbase + (lane & 7) + ((lane >> 3) & 1) * 8;
    const int rx  = lane & 7;
    const int kpa = lane >> 4;                   // A: k-chunk parity per lane group
    const int kpb = (lane >> 3) & 1;             // B: k-chunk parity
    const int jb  = (lane >> 4) & 1;             // B: n-octet within the 16-row group
    const uint32_t aH = sb + OFF_FH + r * 512;
    const uint32_t aL = sb + OFF_FL + r * 512;
    const uint32_t bRow = (uint32_t)((n0 + (lane & 7)) * 512 + jb * 4096);
    const uint32_t bH = sb + OFF_WH + bRow;
    const uint32_t bL = sb + OFF_WL + bRow;
#pragma unroll 2
    for (int kt = 0; kt < 16; kt++) {
        uint32_t aoff = (uint32_t)(((2 * kt + kpa) ^ rx) << 4);
        uint32_t boff = (uint32_t)(((2 * kt + kpb) ^ rx) << 4);
        uint32_t ah0[4], ah1[4], al0[4], al1[4];
        ldmx4(ah0, aH + aoff);
        ldmx4(ah1, aH + 8192 + aoff);            // rows +16
        ldmx4(al0, aL + aoff);
        ldmx4(al1, aL + 8192 + aoff);
#pragma unroll
        for (int jp = 0; jp < 2; jp++) {
            uint32_t bh[4], bl[4];
            ldmx4(bh, bH + jp * 8192 + boff);
            ldmx4(bl, bL + jp * 8192 + boff);
            float* c0 = C  + jp * 8;             // mi = 0
            float* w0 = Cw + jp * 8;
            float* c1 = C  + 16 + jp * 8;        // mi = 1
            float* w1 = Cw + 16 + jp * 8;
            mma16816(c0,     ah0, bh);  mma16816(c0 + 4, ah0, bh + 2);
            mma16816(c1,     ah1, bh);  mma16816(c1 + 4, ah1, bh + 2);
            mma16816(w0,     al0, bh);  mma16816(w0 + 4, al0, bh + 2);
            mma16816(w1,     al1, bh);  mma16816(w1 + 4, al1, bh + 2);
            mma16816(w0,     ah0, bl);  mma16816(w0 + 4, ah0, bl + 2);
            mma16816(w1,     ah1, bl);  mma16816(w1 + 4, ah1, bl + 2);
        }
    }
#pragma unroll
    for (int i = 0; i < 32; i++) C[i] = fmaf(Cw[i], LO_INV, C[i]);
}

// ======================= kernel ============================================
__global__ void __launch_bounds__(NTHREADS, 1)
phase_kernel(const float* __restrict__ x, const float* __restrict__ e_w,
             const float* __restrict__ e_b, const float* __restrict__ d_w,
             const float* __restrict__ d_b, const float* __restrict__ r_w,
             const float* __restrict__ r_b, float* __restrict__ outbuf) {
    extern __shared__ char sm[];
    float* smf = (float*)sm;
    const int tid  = threadIdx.x;
    const int lane = tid & 31;
    const int warp = tid >> 5;
    const int mt = warp >> 2, nq = warp & 3;     // m-group (0..1), n-quarter (0..3)
    const int Rbase = mt * 32, n0 = nq * 32;
    const int gbar = 1 + mt;                     // named barrier id for this group
    const int g  = lane >> 2;
    const int c2 = (lane & 3) * 2;
    const int r0 = Rbase + g;                    // rows r0, r0+8, r0+16, r0+24
    const int grow0 = blockIdx.x * MROWS + r0;
    const uint32_t sb = smem_u32(sm);

    // ---- stage small arrays; compute exact K1 = rowsum(Wcs cos-half) ----
    if (tid < 128) {
        smf[OFF_EW / 4 + tid] = e_w[tid];
        smf[OFF_EB / 4 + tid] = e_b[tid];
        smf[OFF_DB / 4 + tid] = d_b[tid];
        smf[OFF_RW / 4 + tid]       = r_w[tid];
        smf[OFF_RW / 4 + 128 + tid] = r_w[128 + tid];
        smf[OFF_RW / 4 + 256 + tid] = r_w[256 + tid];
        const float4* wr = (const float4*)(d_w + (size_t)tid * 512);
        float s = 0.f;
#pragma unroll 8
        for (int i = 0; i < 32; i++) {
            float4 v = wr[i];
            s += v.x + v.y + v.z + v.w;
        }
        smf[OFF_K1 / 4 + tid] = s;
    }
    if (tid < MROWS) smf[OFF_OUT / 4 + tid] = 0.f;
    if (tid == 0) smf[OFF_RB / 4] = r_b[0];

    stage_w(sm, d_w, 256, tid);                  // Wx = d_w[:, 256:512] (hi+lo)
    __syncthreads();

    float xv[4];
#pragma unroll
    for (int q = 0; q < 4; q++) xv[q] = x[grow0 + 8 * q];

    // ---- xp feats: cos/sin(x*e_w + e_b), 4 rows x 8 cols per thread ----
#pragma unroll
    for (int j = 0; j < 4; j++) {
        int cj = n0 + 8 * j + c2;
        float w0 = smf[OFF_EW / 4 + cj], w1 = smf[OFF_EW / 4 + cj + 1];
        float b0 = smf[OFF_EB / 4 + cj], b1 = smf[OFF_EB / 4 + cj + 1];
#pragma unroll
        for (int q = 0; q < 4; q++) {
            float p0 = fmaf(xv[q], w0, b0), p1 = fmaf(xv[q], w1, b1);
            float s0, c0, s1, c1;
            __sincosf(p0, &s0, &c0); __sincosf(p1, &s1, &c1);
            emit_feats(sm, r0 + 8 * q, cj, c0, c1, s0, s1);
        }
    }
    __syncthreads();

    float C[32];
#pragma unroll
    for (int i = 0; i < 32; i++) C[i] = 0.f;

    gemm3(C, sb, lane, Rbase, n0);               // C = X0 = xp_feats @ Wx^T
    __syncthreads();                             // all reads of Wx/feats done

    // xdb = X0 + d_b; C <- X0 + K1 + d_b (d_b folded into accumulator forever)
    float xdb[32];
#pragma unroll
    for (int mi = 0; mi < 2; mi++)
#pragma unroll
        for (int j = 0; j < 4; j++) {
            int cj = n0 + 8 * j + c2;
            int ci = mi * 16 + j * 4;
            float d0 = smf[OFF_DB / 4 + cj], d1 = smf[OFF_DB / 4 + cj + 1];
            float k0 = smf[OFF_K1 / 4 + cj], k1 = smf[OFF_K1 / 4 + cj + 1];
            xdb[ci + 0] = C[ci + 0] + d0;
            xdb[ci + 1] = C[ci + 1] + d1;
            xdb[ci + 2] = C[ci + 2] + d0;
            xdb[ci + 3] = C[ci + 3] + d1;
            C[ci + 0] += k0 + d0;
            C[ci + 1] += k1 + d1;
            C[ci + 2] += k0 + d0;
            C[ci + 3] += k1 + d1;
        }

    stage_w(sm, d_w, 0, tid);                    // Wcs = d_w[:, 0:256] (hi+lo)
    __syncthreads();                             // Wcs visible; feats tile free

    // Seed anti-phase: group 1 sleeps ~half a step once; group-local barriers
    // preserve the skew, so one group's GEMM overlaps the other's epilogue.
    if (mt == 1) __nanosleep(1500u);

    float* hst = outbuf + NROWS;                 // Hstack [12, B, 128]
    float racc[4] = {0.f, 0.f, 0.f, 0.f};

    // ---- recurrence.  At loop top: ph_t = C + (t-1)*xdb (d_b pre-folded). ----
#pragma unroll 1
    for (int t = 1; t <= NSTEPS; t++) {
        const float tm1 = (float)(t - 1);
        float* hb = hst + (size_t)(t - 1) * HS_STRIDE + (size_t)grow0 * HD;
#pragma unroll
        for (int mi = 0; mi < 2; mi++)
#pragma unroll
            for (int j = 0; j < 4; j++) {
                int cj = n0 + 8 * j + c2;
                int ci = mi * 16 + j * 4;
                float p0 = fmaf(tm1, xdb[ci + 0], C[ci + 0]);
                float p1 = fmaf(tm1, xdb[ci + 1], C[ci + 1]);
                float p2 = fmaf(tm1, xdb[ci + 2], C[ci + 2]);
                float p3 = fmaf(tm1, xdb[ci + 3], C[ci + 3]);
                __stcs((float2*)(hb + (16 * mi) * HD + cj),     make_float2(p0, p1));
                __stcs((float2*)(hb + (16 * mi + 8) * HD + cj), make_float2(p2, p3));
                float s0, cv0, s1, cv1, s2, cv2, s3, cv3;
                __sincosf(p0, &s0, &cv0); __sincosf(p1, &s1, &cv1);
                __sincosf(p2, &s2, &cv2); __sincosf(p3, &s3, &cv3);
                if (t < NSTEPS) {
                    emit_feats(sm, r0 + 16 * mi,     cj, cv0, cv1, s0, s1);
                    emit_feats(sm, r0 + 16 * mi + 8, cj, cv2, cv3, s2, s3);
                } else {
                    // readout: cos*rw0 + sin*rw1 + ph*rw2
                    float w0 = smf[OFF_RW / 4 + cj],       w1 = smf[OFF_RW / 4 + cj + 1];
                    float v0 = smf[OFF_RW / 4 + 128 + cj], v1 = smf[OFF_RW / 4 + 128 + cj + 1];
                    float u0 = smf[OFF_RW / 4 + 256 + cj], u1 = smf[OFF_RW / 4 + 256 + cj + 1];
                    float a0 = racc[2 * mi], a1 = racc[2 * mi + 1];
                    a0 = fmaf(cv0, w0, a0); a0 = fmaf(s0, v0, a0); a0 = fmaf(p0, u0, a0);
                    a0 = fmaf(cv1, w1, a0); a0 = fmaf(s1, v1, a0); a0 = fmaf(p1, u1, a0);
                    a1 = fmaf(cv2, w0, a1); a1 = fmaf(s2, v0, a1); a1 = fmaf(p2, u0, a1);
                    a1 = fmaf(cv3, w1, a1); a1 = fmaf(s3, v1, a1); a1 = fmaf(p3, u1, a1);
                    racc[2 * mi] = a0; racc[2 * mi + 1] = a1;
                }
            }
        if (t < NSTEPS) {
            GROUP_BAR(gbar);                     // group's feats(ph_t) written
            gemm3(C, sb, lane, Rbase, n0);       // C += feats @ Wcs^T
            GROUP_BAR(gbar);                     // group done reading feats
        }
    }

    // ---- reduce readout across quad lanes, then across the 4 n-quarter warps ----
#pragma unroll
    for (int q = 0; q < 4; q++) {
        racc[q] += __shfl_xor_sync(0xffffffffu, racc[q], 1);
        racc[q] += __shfl_xor_sync(0xffffffffu, racc[q], 2);
    }
    if ((lane & 3) == 0) {
        atomicAdd(&smf[OFF_OUT / 4 + r0],      racc[0]);  // row r0      (mi0,q01)
        atomicAdd(&smf[OFF_OUT / 4 + r0 + 8],  racc[1]);  // row r0+8    (mi0,q23)
        atomicAdd(&smf[OFF_OUT / 4 + r0 + 16], racc[2]);  // row r0+16   (mi1,q01)
        atomicAdd(&smf[OFF_OUT / 4 + r0 + 24], racc[3]);  // row r0+24   (mi1,q23)
    }
    __syncthreads();
    if (tid < MROWS)
        outbuf[blockIdx.x * MROWS + tid] = smf[OFF_OUT / 4 + tid] + smf[OFF_RB / 4];
}

extern "C" void kernel_launch(void* const* d_in, const int* in_sizes, int n_in,
                              void* d_out, int out_size) {
    const float* x   = (const float*)d_in[0];
    const float* e_w = (const float*)d_in[1];
    const float* e_b = (const float*)d_in[2];
    const float* d_w = (const float*)d_in[3];
    const float* d_b = (const float*)d_in[4];
    const float* r_w = (const float*)d_in[5];
    const float* r_b = (const float*)d_in[6];
    float* out = (float*)d_out;

    cudaFuncSetAttribute(phase_kernel,
                         cudaFuncAttributeMaxDynamicSharedMemorySize, SMEM_TOTAL);
    phase_kernel<<<NBLK, NTHREADS, SMEM_TOTAL>>>(x, e_w, e_b, d_w, d_b, r_w, r_b, out);
}

// round 11
// speedup vs baseline: 1.1167x; 1.0027x over previous
#include <cuda_runtime.h>
#include <cuda_fp16.h>
#include <cstdint>

#define NROWS   131072
#define HD      128
#define NSTEPS  12
#define MROWS   64
#define NBLK    (NROWS / MROWS)
#define NTHREADS 512
#define HS_STRIDE ((size_t)NROWS * HD)
#define LO_SCALE   1024.0f
#define LO_INV     (1.0f / 1024.0f)

// ---------------- SMEM layout (byte offsets) -------------------------------
// Big tiles: rows x 512 bytes (256 fp16), 16B-chunk swizzle: chunk ^= (row&7)
// K layout is INTERLEAVED: k' = 2h holds cos/W_cos col h, k' = 2h+1 holds sin/W_sin col h.
#define OFF_WH   0        // W hi fp16: 128(n) x 256(k')    64 KB
#define OFF_WL   65536    // W lo*1024 fp16                 64 KB
#define OFF_FH   131072   // feats hi fp16: 64(m) x 256(k') 32 KB
#define OFF_FL   163840   // feats lo*1024 fp16             32 KB
#define OFF_EW   196608
#define OFF_EB   197120
#define OFF_DB   197632
#define OFF_RW   198144   // 3*128 floats
#define OFF_OUT  199680   // 64 floats
#define OFF_RB   199936
#define OFF_K1   200192   // 128 floats: rowsum of Wcs cos-half (exact fp32)
#define SMEM_TOTAL 200704

// ======================= low-level helpers =================================
static __device__ __forceinline__ uint32_t smem_u32(const void* p) {
    uint32_t a;
    asm("{ .reg .u64 t; cvta.to.shared.u64 t, %1; cvt.u32.u64 %0, t; }" : "=r"(a) : "l"(p));
    return a;
}
static __device__ __forceinline__ void ldmx4(uint32_t* a, uint32_t addr) {
    asm volatile("ldmatrix.sync.aligned.m8n8.x4.shared.b16 {%0,%1,%2,%3}, [%4];"
                 : "=r"(a[0]), "=r"(a[1]), "=r"(a[2]), "=r"(a[3]) : "r"(addr));
}
// fp32-accumulator mma (main pass)
static __device__ __forceinline__ void mma16816(float* c, const uint32_t* a, const uint32_t* b) {
    asm volatile("mma.sync.aligned.m16n8k16.row.col.f32.f16.f16.f32 "
                 "{%0,%1,%2,%3}, {%4,%5,%6,%7}, {%8,%9}, {%0,%1,%2,%3};"
                 : "+f"(c[0]), "+f"(c[1]), "+f"(c[2]), "+f"(c[3])
                 : "r"(a[0]), "r"(a[1]), "r"(a[2]), "r"(a[3]), "r"(b[0]), "r"(b[1]));
}
// fp16-accumulator mma (correction passes; magnitudes O(1), rounding /1024'd)
static __device__ __forceinline__ void mma16816_h(uint32_t* d, const uint32_t* a, const uint32_t* b) {
    asm volatile("mma.sync.aligned.m16n8k16.row.col.f16.f16.f16.f16 "
                 "{%0,%1}, {%2,%3,%4,%5}, {%6,%7}, {%0,%1};"
                 : "+r"(d[0]), "+r"(d[1])
                 : "r"(a[0]), "r"(a[1]), "r"(a[2]), "r"(a[3]), "r"(b[0]), "r"(b[1]));
}

// mt-group barrier: the 128 threads (4 warps) of m-tile group mt
#define GROUP_BAR(id) asm volatile("bar.sync %0, 128;" :: "r"(id) : "memory")

// hi/lo fp16 split of a pair (a -> low half, b -> high half); lo scaled by LO_SCALE
static __device__ __forceinline__ void split2(float a, float b, uint32_t& hi, uint32_t& lo) {
    __half2 h2 = __floats2half2_rn(a, b);
    float2 f2 = __half22float2(h2);
    __half2 l2 = __floats2half2_rn((a - f2.x) * LO_SCALE, (b - f2.y) * LO_SCALE);
    hi = *reinterpret_cast<uint32_t*>(&h2);
    lo = *reinterpret_cast<uint32_t*>(&l2);
}

// 8B store into a swizzled 512B-row tile (cbyte must be 8B-aligned)
static __device__ __forceinline__ void st8sw(char* sm, int off, int r, int cbyte, uint2 v) {
    uint32_t chunk = ((uint32_t)(cbyte >> 4)) ^ (uint32_t)(r & 7);
    *(uint2*)(sm + off + r * 512 + (chunk << 4) + (cbyte & 15)) = v;
}

// Write interleaved (cos,sin) hi+lo for row r, columns cj, cj+1 (cj even):
// bytes [4cj, 4cj+8) = fp16 {c0, s0, c1, s1}.  One STS.64 per tile.
static __device__ __forceinline__ void emit_feats(char* sm, int r, int cj,
                                                  float c0, float c1, float s0, float s1) {
    uint32_t h0, l0, h1, l1;
    split2(c0, s0, h0, l0);
    split2(c1, s1, h1, l1);
    st8sw(sm, OFF_FH, r, 4 * cj, make_uint2(h0, h1));
    st8sw(sm, OFF_FL, r, 4 * cj, make_uint2(l0, l1));
}

// Stage 128x256 fp32 weight block (d_w cols [colbase, colbase+256)) as fp16
// hi + scaled-lo, INTERLEAVED k' = 2h (cos col h), 2h+1 (sin col h).
// 512 threads: thread = (row r = tid>>2, col-quarter q = tid&3).
static __device__ __forceinline__ void stage_w(char* sm, const float* __restrict__ dw,
                                               int colbase, int tid) {
    int r = tid >> 2, q = tid & 3;
    const float* base = dw + (size_t)r * 512 + colbase;
    const float4* csrc = (const float4*)(base + 32 * q);        // cos block cols
    const float4* ssrc = (const float4*)(base + 128 + 32 * q);  // sin block cols
    int rx = r & 7;
    char* dh = sm + OFF_WH + r * 512;
    char* dl = sm + OFF_WL + r * 512;
#pragma unroll
    for (int i = 0; i < 8; i++) {
        float4 c = csrc[i];
        float4 s = ssrc[i];
        uint4 h, l;
        split2(c.x, s.x, h.x, l.x);
        split2(c.y, s.y, h.y, l.y);
        split2(c.z, s.z, h.z, l.z);
        split2(c.w, s.w, h.w, l.w);
        uint32_t chunk = (uint32_t)((q * 8 + i) ^ rx);
        *(uint4*)(dh + (chunk << 4)) = h;
        *(uint4*)(dl + (chunk << 4)) = l;
    }
}

// 3-pass split GEMM, K=256, warp tile 16x32.
// C(f32) += Ah@Wh^T;  Cw(f16) += Al@Wh^T + Ah@Wl^T;  C += Cw/1024.
static __device__ __forceinline__ void gemm3(float* C, uint32_t sb, int lane,
                                             int Rbase, int n0) {
    uint32_t Cw[8] = {0, 0, 0, 0, 0, 0, 0, 0};
    const int r   = Rbase + (lane & 7) + ((lane >> 3) & 1) * 8;
    const int rx  = lane & 7;
    const int kpa = lane >> 4;                   // A: k-chunk parity per lane group
    const int kpb = (lane >> 3) & 1;             // B: k-chunk parity
    const int jb  = (lane >> 4) & 1;             // B: n-octet within the 16-row group
    const uint32_t aH = sb + OFF_FH + r * 512;
    const uint32_t aL = sb + OFF_FL + r * 512;
    const uint32_t bRow = (uint32_t)((n0 + (lane & 7)) * 512 + jb * 4096);
    const uint32_t bH = sb + OFF_WH + bRow;
    const uint32_t bL = sb + OFF_WL + bRow;
#pragma unroll 4
    for (int kt = 0; kt < 16; kt++) {
        uint32_t aoff = (uint32_t)(((2 * kt + kpa) ^ rx) << 4);
        uint32_t boff = (uint32_t)(((2 * kt + kpb) ^ rx) << 4);
        uint32_t ah[4], al[4];
        ldmx4(ah, aH + aoff);
        ldmx4(al, aL + aoff);
#pragma unroll
        for (int jp = 0; jp < 2; jp++) {
            uint32_t bh[4], bl[4];
            ldmx4(bh, bH + jp * 8192 + boff);
            ldmx4(bl, bL + jp * 8192 + boff);
            mma16816(C + 8 * jp,     ah, bh);
            mma16816(C + 8 * jp + 4, ah, bh + 2);
            mma16816_h(&Cw[jp * 4],     al, bh);
            mma16816_h(&Cw[jp * 4],     ah, bl);
            mma16816_h(&Cw[jp * 4 + 2], al, bh + 2);
            mma16816_h(&Cw[jp * 4 + 2], ah, bl + 2);
        }
    }
#pragma unroll
    for (int jp = 0; jp < 2; jp++)
#pragma unroll
        for (int hf = 0; hf < 2; hf++) {
            int bi = jp * 8 + hf * 4;
            int wi = jp * 4 + hf * 2;
            float2 f0 = __half22float2(*reinterpret_cast<__half2*>(&Cw[wi]));
            float2 f1 = __half22float2(*reinterpret_cast<__half2*>(&Cw[wi + 1]));
            C[bi + 0] = fmaf(f0.x, LO_INV, C[bi + 0]);
            C[bi + 1] = fmaf(f0.y, LO_INV, C[bi + 1]);
            C[bi + 2] = fmaf(f1.x, LO_INV, C[bi + 2]);
            C[bi + 3] = fmaf(f1.y, LO_INV, C[bi + 3]);
        }
}

// ======================= kernel ============================================
__global__ void __launch_bounds__(NTHREADS, 1)
phase_kernel(const float* __restrict__ x, const float* __restrict__ e_w,
             const float* __restrict__ e_b, const float* __restrict__ d_w,
             const float* __restrict__ d_b, const float* __restrict__ r_w,
             const float* __restrict__ r_b, float* __restrict__ outbuf) {
    extern __shared__ char sm[];
    float* smf = (float*)sm;
    const int tid  = threadIdx.x;
    const int lane = tid & 31;
    const int warp = tid >> 5;
    const int mt = warp >> 2, nq = warp & 3;     // m-group (0..3), n-quarter (0..3)
    const int Rbase = mt * 16, n0 = nq * 32;
    const int gbar = 1 + mt;                     // named barrier id for this group
    const int g  = lane >> 2;
    const int c2 = (lane & 3) * 2;
    const int r0 = Rbase + g;                    // local rows r0, r0+8
    const int grow0 = blockIdx.x * MROWS + r0;
    const uint32_t sb = smem_u32(sm);

    // ---- stage small arrays; compute exact K1 = rowsum(Wcs cos-half) ----
    if (tid < 128) {
        smf[OFF_EW / 4 + tid] = e_w[tid];
        smf[OFF_EB / 4 + tid] = e_b[tid];
        smf[OFF_DB / 4 + tid] = d_b[tid];
        smf[OFF_RW / 4 + tid]       = r_w[tid];
        smf[OFF_RW / 4 + 128 + tid] = r_w[128 + tid];
        smf[OFF_RW / 4 + 256 + tid] = r_w[256 + tid];
        const float4* wr = (const float4*)(d_w + (size_t)tid * 512);
        float s = 0.f;
#pragma unroll 8
        for (int i = 0; i < 32; i++) {
            float4 v = wr[i];
            s += v.x + v.y + v.z + v.w;
        }
        smf[OFF_K1 / 4 + tid] = s;
    }
    if (tid < MROWS) smf[OFF_OUT / 4 + tid] = 0.f;
    if (tid == 0) smf[OFF_RB / 4] = r_b[0];

    stage_w(sm, d_w, 256, tid);                  // Wx = d_w[:, 256:512] (hi+lo)
    __syncthreads();

    const float x0 = x[grow0];
    const float x1 = x[grow0 + 8];

    // ---- xp feats: cos/sin(x*e_w + e_b) for this thread's (rows, cols) ----
#pragma unroll
    for (int j = 0; j < 4; j++) {
        int cj = n0 + 8 * j + c2;
        float w0 = smf[OFF_EW / 4 + cj], w1 = smf[OFF_EW / 4 + cj + 1];
        float b0 = smf[OFF_EB / 4 + cj], b1 = smf[OFF_EB / 4 + cj + 1];
        float p00 = fmaf(x0, w0, b0), p01 = fmaf(x0, w1, b1);
        float p10 = fmaf(x1, w0, b0), p11 = fmaf(x1, w1, b1);
        float s00, c00, s01, c01, s10, c10, s11, c11;
        __sincosf(p00, &s00, &c00); __sincosf(p01, &s01, &c01);
        __sincosf(p10, &s10, &c10); __sincosf(p11, &s11, &c11);
        emit_feats(sm, r0,     cj, c00, c01, s00, s01);
        emit_feats(sm, r0 + 8, cj, c10, c11, s10, s11);
    }
    __syncthreads();

    float C[16];
#pragma unroll
    for (int i = 0; i < 16; i++) C[i] = 0.f;

    gemm3(C, sb, lane, Rbase, n0);               // C = X0 = xp_feats @ Wx^T
    __syncthreads();                             // all reads of Wx/feats done

    // xdb = X0 + d_b; C <- X0 + K1 + d_b (t=1 GEMM + bias pre-folded)
    float xdb[16];
#pragma unroll
    for (int j = 0; j < 4; j++) {
        int cj = n0 + 8 * j + c2;
        float d0 = smf[OFF_DB / 4 + cj], d1 = smf[OFF_DB / 4 + cj + 1];
        float k0 = smf[OFF_K1 / 4 + cj], k1 = smf[OFF_K1 / 4 + cj + 1];
        xdb[4 * j + 0] = C[4 * j + 0] + d0;
        xdb[4 * j + 1] = C[4 * j + 1] + d1;
        xdb[4 * j + 2] = C[4 * j + 2] + d0;
        xdb[4 * j + 3] = C[4 * j + 3] + d1;
        C[4 * j + 0] += k0 + d0;
        C[4 * j + 1] += k1 + d1;
        C[4 * j + 2] += k0 + d0;
        C[4 * j + 3] += k1 + d1;
    }

    stage_w(sm, d_w, 0, tid);                    // Wcs = d_w[:, 0:256] (hi+lo)
    __syncthreads();                             // Wcs visible; feats tile free

    // Seed anti-phase: group mt delays mt/4 of a step once; group-local
    // barriers preserve the skew so GEMM overlaps other groups' epilogues.
    if (mt) __nanosleep((unsigned)(mt * 1400));

    float* hst = outbuf + NROWS;                 // Hstack [12, B, 128]
    float racc0 = 0.f, racc1 = 0.f;

    // ---- recurrence.  At loop top: ph_t = C + (t-1)*xdb (d_b pre-folded). ----
#pragma unroll 1
    for (int t = 1; t <= NSTEPS; t++) {
        const float tm1 = (float)(t - 1);
        float* h0 = hst + (size_t)(t - 1) * HS_STRIDE + (size_t)grow0 * HD;
        float* h1 = h0 + 8 * HD;
#pragma unroll
        for (int j = 0; j < 4; j++) {
            int cj = n0 + 8 * j + c2;
            float p0 = fmaf(tm1, xdb[4 * j + 0], C[4 * j + 0]);
            float p1 = fmaf(tm1, xdb[4 * j + 1], C[4 * j + 1]);
            float p2 = fmaf(tm1, xdb[4 * j + 2], C[4 * j + 2]);
            float p3 = fmaf(tm1, xdb[4 * j + 3], C[4 * j + 3]);
            __stcs((float2*)(h0 + cj), make_float2(p0, p1));
            __stcs((float2*)(h1 + cj), make_float2(p2, p3));
            float s0, cv0, s1, cv1, s2, cv2, s3, cv3;
            __sincosf(p0, &s0, &cv0); __sincosf(p1, &s1, &cv1);
            __sincosf(p2, &s2, &cv2); __sincosf(p3, &s3, &cv3);
            if (t < NSTEPS) {
                emit_feats(sm, r0,     cj, cv0, cv1, s0, s1);
                emit_feats(sm, r0 + 8, cj, cv2, cv3, s2, s3);
            } else {
                // readout: cos*rw0 + sin*rw1 + ph*rw2
                float w0 = smf[OFF_RW / 4 + cj],       w1 = smf[OFF_RW / 4 + cj + 1];
                float v0 = smf[OFF_RW / 4 + 128 + cj], v1 = smf[OFF_RW / 4 + 128 + cj + 1];
                float u0 = smf[OFF_RW / 4 + 256 + cj], u1 = smf[OFF_RW / 4 + 256 + cj + 1];
                racc0 = fmaf(cv0, w0, racc0); racc0 = fmaf(s0, v0, racc0); racc0 = fmaf(p0, u0, racc0);
                racc0 = fmaf(cv1, w1, racc0); racc0 = fmaf(s1, v1, racc0); racc0 = fmaf(p1, u1, racc0);
                racc1 = fmaf(cv2, w0, racc1); racc1 = fmaf(s2, v0, racc1); racc1 = fmaf(p2, u0, racc1);
                racc1 = fmaf(cv3, w1, racc1); racc1 = fmaf(s3, v1, racc1); racc1 = fmaf(p3, u1, racc1);
            }
        }
        if (t < NSTEPS) {
            GROUP_BAR(gbar);                     // group's feats(ph_t) written
            gemm3(C, sb, lane, Rbase, n0);       // C += feats @ Wcs^T
            GROUP_BAR(gbar);                     // group done reading feats
        }
    }

    // ---- reduce readout across quad lanes, then across the 4 n-quarter warps ----
    racc0 += __shfl_xor_sync(0xffffffffu, racc0, 1);
    racc0 += __shfl_xor_sync(0xffffffffu, racc0, 2);
    racc1 += __shfl_xor_sync(0xffffffffu, racc1, 1);
    racc1 += __shfl_xor_sync(0xffffffffu, racc1, 2);
    if ((lane & 3) == 0) {
        atomicAdd(&smf[OFF_OUT / 4 + r0], racc0);
        atomicAdd(&smf[OFF_OUT / 4 + r0 + 8], racc1);
    }
    __syncthreads();
    if (tid < MROWS)
        outbuf[blockIdx.x * MROWS + tid] = smf[OFF_OUT / 4 + tid] + smf[OFF_RB / 4];
}

extern "C" void kernel_launch(void* const* d_in, const int* in_sizes, int n_in,
                              void* d_out, int out_size) {
    const float* x   = (const float*)d_in[0];
    const float* e_w = (const float*)d_in[1];
    const float* e_b = (const float*)d_in[2];
    const float* d_w = (const float*)d_in[3];
    const float* d_b = (const float*)d_in[4];
    const float* r_w = (const float*)d_in[5];
    const float* r_b = (const float*)d_in[6];
    float* out = (float*)d_out;

    cudaFuncSetAttribute(phase_kernel,
                         cudaFuncAttributeMaxDynamicSharedMemorySize, SMEM_TOTAL);
    phase_kernel<<<NBLK, NTHREADS, SMEM_TOTAL>>>(x, e_w, e_b, d_w, d_b, r_w, r_b, out);
}

// round 12
// speedup vs baseline: 1.1710x; 1.0486x over previous
#include <cuda_runtime.h>
#include <cuda_fp16.h>
#include <cstdint>

#define NROWS   131072
#define HD      128
#define NSTEPS  12
#define MROWS   64
#define NBLK    (NROWS / MROWS)
#define NTHREADS 256
#define HS_STRIDE ((size_t)NROWS * HD)
#define LO_SCALE   1024.0f
#define LO_INV     (1.0f / 1024.0f)

// ---------------- SMEM layout (byte offsets) -------------------------------
// Big tiles: rows x 512 bytes (256 fp16), 16B-chunk swizzle: chunk ^= (row&7)
// K is INTERLEAVED: k' = 2h holds cos/W_cos col h, k' = 2h+1 holds sin/W_sin col h.
#define OFF_WH   0        // W hi fp16: 128(n) x 256(k')    64 KB
#define OFF_WL   65536    // W lo*1024 fp16                 64 KB
#define OFF_FH   131072   // feats hi fp16: 64(m) x 256(k') 32 KB
#define OFF_FL   163840   // feats lo*1024 fp16             32 KB
#define OFF_EW   196608
#define OFF_EB   197120
#define OFF_DB   197632
#define OFF_RW   198144   // 3*128 floats
#define OFF_OUT  199680   // 64 floats
#define OFF_RB   199936
#define OFF_K1   200192   // 128 floats: rowsum of Wcs cos-half (exact fp32)
#define SMEM_TOTAL 200704

// ======================= low-level helpers =================================
static __device__ __forceinline__ uint32_t smem_u32(const void* p) {
    uint32_t a;
    asm("{ .reg .u64 t; cvta.to.shared.u64 t, %1; cvt.u32.u64 %0, t; }" : "=r"(a) : "l"(p));
    return a;
}
static __device__ __forceinline__ void ldmx4(uint32_t* a, uint32_t addr) {
    asm volatile("ldmatrix.sync.aligned.m8n8.x4.shared.b16 {%0,%1,%2,%3}, [%4];"
                 : "=r"(a[0]), "=r"(a[1]), "=r"(a[2]), "=r"(a[3]) : "r"(addr));
}
// fp32-accumulator mma (main pass)
static __device__ __forceinline__ void mma16816(float* c, const uint32_t* a, const uint32_t* b) {
    asm volatile("mma.sync.aligned.m16n8k16.row.col.f32.f16.f16.f32 "
                 "{%0,%1,%2,%3}, {%4,%5,%6,%7}, {%8,%9}, {%0,%1,%2,%3};"
                 : "+f"(c[0]), "+f"(c[1]), "+f"(c[2]), "+f"(c[3])
                 : "r"(a[0]), "r"(a[1]), "r"(a[2]), "r"(a[3]), "r"(b[0]), "r"(b[1]));
}
// fp16-accumulator mma (correction passes; magnitudes O(1), rounding /1024'd)
static __device__ __forceinline__ void mma16816_h(uint32_t* d, const uint32_t* a, const uint32_t* b) {
    asm volatile("mma.sync.aligned.m16n8k16.row.col.f16.f16.f16.f16 "
                 "{%0,%1}, {%2,%3,%4,%5}, {%6,%7}, {%0,%1};"
                 : "+r"(d[0]), "+r"(d[1])
                 : "r"(a[0]), "r"(a[1]), "r"(a[2]), "r"(a[3]), "r"(b[0]), "r"(b[1]));
}

// mt-group barrier: the 128 threads (4 warps) of m-tile group mt
#define GROUP_BAR(id) asm volatile("bar.sync %0, 128;" :: "r"(id) : "memory")

// hi/lo fp16 split of a pair (a -> low half, b -> high half); lo scaled by LO_SCALE
static __device__ __forceinline__ void split2(float a, float b, uint32_t& hi, uint32_t& lo) {
    __half2 h2 = __floats2half2_rn(a, b);
    float2 f2 = __half22float2(h2);
    __half2 l2 = __floats2half2_rn((a - f2.x) * LO_SCALE, (b - f2.y) * LO_SCALE);
    hi = *reinterpret_cast<uint32_t*>(&h2);
    lo = *reinterpret_cast<uint32_t*>(&l2);
}

// 8B store into a swizzled 512B-row tile (cbyte must be 8B-aligned)
static __device__ __forceinline__ void st8sw(char* sm, int off, int r, int cbyte, uint2 v) {
    uint32_t chunk = ((uint32_t)(cbyte >> 4)) ^ (uint32_t)(r & 7);
    *(uint2*)(sm + off + r * 512 + (chunk << 4) + (cbyte & 15)) = v;
}

// Write interleaved (cos,sin) hi+lo for row r, columns cj, cj+1 (cj even):
// bytes [4cj, 4cj+8) = fp16 {c0, s0, c1, s1}.  One STS.64 per tile.
static __device__ __forceinline__ void emit_feats(char* sm, int r, int cj,
                                                  float c0, float c1, float s0, float s1) {
    uint32_t h0, l0, h1, l1;
    split2(c0, s0, h0, l0);
    split2(c1, s1, h1, l1);
    st8sw(sm, OFF_FH, r, 4 * cj, make_uint2(h0, h1));
    st8sw(sm, OFF_FL, r, 4 * cj, make_uint2(l0, l1));
}

// Stage 128x256 fp32 weight block (d_w cols [colbase, colbase+256)) as fp16
// hi + scaled-lo, INTERLEAVED k' = 2h (cos col h), 2h+1 (sin col h).
// 256 threads: thread = (row r = tid>>1, k-half = tid&1).
static __device__ __forceinline__ void stage_w(char* sm, const float* __restrict__ dw,
                                               int colbase, int tid) {
    int r = tid >> 1, half = tid & 1;
    const float* base = dw + (size_t)r * 512 + colbase;
    const float4* csrc = (const float4*)(base + 64 * half);        // cos cols h
    const float4* ssrc = (const float4*)(base + 128 + 64 * half);  // sin cols h
    int rx = r & 7;
    char* dh = sm + OFF_WH + r * 512;
    char* dl = sm + OFF_WL + r * 512;
#pragma unroll
    for (int i = 0; i < 16; i++) {
        float4 c = csrc[i];
        float4 s = ssrc[i];
        uint4 h, l;
        split2(c.x, s.x, h.x, l.x);
        split2(c.y, s.y, h.y, l.y);
        split2(c.z, s.z, h.z, l.z);
        split2(c.w, s.w, h.w, l.w);
        uint32_t chunk = (uint32_t)((half * 16 + i) ^ rx);
        *(uint4*)(dh + (chunk << 4)) = h;
        *(uint4*)(dl + (chunk << 4)) = l;
    }
}

// 3-pass split GEMM, K=256, warp tile 32x32.
// C(f32) += Ah@Wh^T;  Cw(f16) += Al@Wh^T + Ah@Wl^T;  C += Cw/1024.
// C layout: C[mi*16 + j*4 + q]; Cw[mi*8 + jp*4 + hf*2 + r].
static __device__ __forceinline__ void gemm3(float* C, uint32_t sb, int lane,
                                             int Rbase, int n0) {
    uint32_t Cw[16];
#pragma unroll
    for (int i = 0; i < 16; i++) Cw[i] = 0u;
    const int r   = Rbase + (lane & 7) + ((lane >> 3) & 1) * 8;
    const int rx  = lane & 7;
    const int kpa = lane >> 4;                   // A: k-chunk parity per lane group
    const int kpb = (lane >> 3) & 1;             // B: k-chunk parity
    const int jb  = (lane >> 4) & 1;             // B: n-octet within the 16-col group
    const uint32_t aH = sb + OFF_FH + r * 512;
    const uint32_t aL = sb + OFF_FL + r * 512;
    const uint32_t bRow = (uint32_t)((n0 + (lane & 7)) * 512 + jb * 4096);
    const uint32_t bH = sb + OFF_WH + bRow;
    const uint32_t bL = sb + OFF_WL + bRow;
#pragma unroll 2
    for (int kt = 0; kt < 16; kt++) {
        uint32_t aoff = (uint32_t)(((2 * kt + kpa) ^ rx) << 4);
        uint32_t boff = (uint32_t)(((2 * kt + kpb) ^ rx) << 4);
        uint32_t ah0[4], ah1[4], al0[4], al1[4];
        ldmx4(ah0, aH + aoff);
        ldmx4(ah1, aH + 8192 + aoff);            // rows +16
        ldmx4(al0, aL + aoff);
        ldmx4(al1, aL + 8192 + aoff);
#pragma unroll
        for (int jp = 0; jp < 2; jp++) {
            uint32_t bh[4], bl[4];
            ldmx4(bh, bH + jp * 8192 + boff);
            ldmx4(bl, bL + jp * 8192 + boff);
            float* c0 = C + jp * 8;              // mi = 0
            float* c1 = C + 16 + jp * 8;         // mi = 1
            uint32_t* w0 = Cw + jp * 4;          // mi = 0
            uint32_t* w1 = Cw + 8 + jp * 4;      // mi = 1
            mma16816(c0,     ah0, bh);  mma16816(c0 + 4, ah0, bh + 2);
            mma16816(c1,     ah1, bh);  mma16816(c1 + 4, ah1, bh + 2);
            mma16816_h(w0,     al0, bh);  mma16816_h(w0,     ah0, bl);
            mma16816_h(w0 + 2, al0, bh + 2);  mma16816_h(w0 + 2, ah0, bl + 2);
            mma16816_h(w1,     al1, bh);  mma16816_h(w1,     ah1, bl);
            mma16816_h(w1 + 2, al1, bh + 2);  mma16816_h(w1 + 2, ah1, bl + 2);
        }
    }
#pragma unroll
    for (int mi = 0; mi < 2; mi++)
#pragma unroll
        for (int jp = 0; jp < 2; jp++)
#pragma unroll
            for (int hf = 0; hf < 2; hf++) {
                int bi = mi * 16 + jp * 8 + hf * 4;
                int wi = mi * 8 + jp * 4 + hf * 2;
                float2 f0 = __half22float2(*reinterpret_cast<__half2*>(&Cw[wi]));
                float2 f1 = __half22float2(*reinterpret_cast<__half2*>(&Cw[wi + 1]));
                C[bi + 0] = fmaf(f0.x, LO_INV, C[bi + 0]);
                C[bi + 1] = fmaf(f0.y, LO_INV, C[bi + 1]);
                C[bi + 2] = fmaf(f1.x, LO_INV, C[bi + 2]);
                C[bi + 3] = fmaf(f1.y, LO_INV, C[bi + 3]);
            }
}

// ======================= kernel ============================================
__global__ void __launch_bounds__(NTHREADS, 1)
phase_kernel(const float* __restrict__ x, const float* __restrict__ e_w,
             const float* __restrict__ e_b, const float* __restrict__ d_w,
             const float* __restrict__ d_b, const float* __restrict__ r_w,
             const float* __restrict__ r_b, float* __restrict__ outbuf) {
    extern __shared__ char sm[];
    float* smf = (float*)sm;
    const int tid  = threadIdx.x;
    const int lane = tid & 31;
    const int warp = tid >> 5;
    const int mt = warp >> 2, nq = warp & 3;     // m-group (0..1), n-quarter (0..3)
    const int Rbase = mt * 32, n0 = nq * 32;
    const int gbar = 1 + mt;                     // named barrier id for this group
    const int g  = lane >> 2;
    const int c2 = (lane & 3) * 2;
    const int r0 = Rbase + g;                    // rows r0, r0+8, r0+16, r0+24
    const int grow0 = blockIdx.x * MROWS + r0;
    const uint32_t sb = smem_u32(sm);

    // ---- stage small arrays; compute exact K1 = rowsum(Wcs cos-half) ----
    if (tid < 128) {
        smf[OFF_EW / 4 + tid] = e_w[tid];
        smf[OFF_EB / 4 + tid] = e_b[tid];
        smf[OFF_DB / 4 + tid] = d_b[tid];
        smf[OFF_RW / 4 + tid]       = r_w[tid];
        smf[OFF_RW / 4 + 128 + tid] = r_w[128 + tid];
        smf[OFF_RW / 4 + 256 + tid] = r_w[256 + tid];
        const float4* wr = (const float4*)(d_w + (size_t)tid * 512);
        float s = 0.f;
#pragma unroll 8
        for (int i = 0; i < 32; i++) {
            float4 v = wr[i];
            s += v.x + v.y + v.z + v.w;
        }
        smf[OFF_K1 / 4 + tid] = s;
    }
    if (tid < MROWS) smf[OFF_OUT / 4 + tid] = 0.f;
    if (tid == 0) smf[OFF_RB / 4] = r_b[0];

    stage_w(sm, d_w, 256, tid);                  // Wx = d_w[:, 256:512] (hi+lo)
    __syncthreads();

    float xv[4];
#pragma unroll
    for (int q = 0; q < 4; q++) xv[q] = x[grow0 + 8 * q];

    // ---- xp feats: cos/sin(x*e_w + e_b), 4 rows x 8 cols per thread ----
#pragma unroll
    for (int j = 0; j < 4; j++) {
        int cj = n0 + 8 * j + c2;
        float w0 = smf[OFF_EW / 4 + cj], w1 = smf[OFF_EW / 4 + cj + 1];
        float b0 = smf[OFF_EB / 4 + cj], b1 = smf[OFF_EB / 4 + cj + 1];
#pragma unroll
        for (int q = 0; q < 4; q++) {
            float p0 = fmaf(xv[q], w0, b0), p1 = fmaf(xv[q], w1, b1);
            float s0, c0, s1, c1;
            __sincosf(p0, &s0, &c0); __sincosf(p1, &s1, &c1);
            emit_feats(sm, r0 + 8 * q, cj, c0, c1, s0, s1);
        }
    }
    __syncthreads();

    float C[32];
#pragma unroll
    for (int i = 0; i < 32; i++) C[i] = 0.f;

    gemm3(C, sb, lane, Rbase, n0);               // C = X0 = xp_feats @ Wx^T
    __syncthreads();                             // all reads of Wx/feats done

    // xdb = X0 + d_b; C <- X0 + K1 + d_b (t=1 GEMM + bias pre-folded)
    float xdb[32];
#pragma unroll
    for (int mi = 0; mi < 2; mi++)
#pragma unroll
        for (int j = 0; j < 4; j++) {
            int cj = n0 + 8 * j + c2;
            int ci = mi * 16 + j * 4;
            float d0 = smf[OFF_DB / 4 + cj], d1 = smf[OFF_DB / 4 + cj + 1];
            float k0 = smf[OFF_K1 / 4 + cj], k1 = smf[OFF_K1 / 4 + cj + 1];
            xdb[ci + 0] = C[ci + 0] + d0;
            xdb[ci + 1] = C[ci + 1] + d1;
            xdb[ci + 2] = C[ci + 2] + d0;
            xdb[ci + 3] = C[ci + 3] + d1;
            C[ci + 0] += k0 + d0;
            C[ci + 1] += k1 + d1;
            C[ci + 2] += k0 + d0;
            C[ci + 3] += k1 + d1;
        }

    stage_w(sm, d_w, 0, tid);                    // Wcs = d_w[:, 0:256] (hi+lo)
    __syncthreads();                             // Wcs visible; feats tile free

    // Seed anti-phase: group 1 delays ~the epilogue width once; group-local
    // barriers preserve the skew so its GEMM overlaps group 0's epilogue.
    if (mt == 1) __nanosleep(2000u);

    float* hst = outbuf + NROWS;                 // Hstack [12, B, 128]
    float racc[4] = {0.f, 0.f, 0.f, 0.f};

    // ---- recurrence.  At loop top: ph_t = C + (t-1)*xdb (d_b pre-folded). ----
#pragma unroll 1
    for (int t = 1; t <= NSTEPS; t++) {
        const float tm1 = (float)(t - 1);
        float* hb = hst + (size_t)(t - 1) * HS_STRIDE + (size_t)grow0 * HD;
#pragma unroll
        for (int mi = 0; mi < 2; mi++)
#pragma unroll
            for (int j = 0; j < 4; j++) {
                int cj = n0 + 8 * j + c2;
                int ci = mi * 16 + j * 4;
                float p0 = fmaf(tm1, xdb[ci + 0], C[ci + 0]);
                float p1 = fmaf(tm1, xdb[ci + 1], C[ci + 1]);
                float p2 = fmaf(tm1, xdb[ci + 2], C[ci + 2]);
                float p3 = fmaf(tm1, xdb[ci + 3], C[ci + 3]);
                __stcs((float2*)(hb + (16 * mi) * HD + cj),     make_float2(p0, p1));
                __stcs((float2*)(hb + (16 * mi + 8) * HD + cj), make_float2(p2, p3));
                float s0, cv0, s1, cv1, s2, cv2, s3, cv3;
                __sincosf(p0, &s0, &cv0); __sincosf(p1, &s1, &cv1);
                __sincosf(p2, &s2, &cv2); __sincosf(p3, &s3, &cv3);
                if (t < NSTEPS) {
                    emit_feats(sm, r0 + 16 * mi,     cj, cv0, cv1, s0, s1);
                    emit_feats(sm, r0 + 16 * mi + 8, cj, cv2, cv3, s2, s3);
                } else {
                    // readout: cos*rw0 + sin*rw1 + ph*rw2
                    float w0 = smf[OFF_RW / 4 + cj],       w1 = smf[OFF_RW / 4 + cj + 1];
                    float v0 = smf[OFF_RW / 4 + 128 + cj], v1 = smf[OFF_RW / 4 + 128 + cj + 1];
                    float u0 = smf[OFF_RW / 4 + 256 + cj], u1 = smf[OFF_RW / 4 + 256 + cj + 1];
                    float a0 = racc[2 * mi], a1 = racc[2 * mi + 1];
                    a0 = fmaf(cv0, w0, a0); a0 = fmaf(s0, v0, a0); a0 = fmaf(p0, u0, a0);
                    a0 = fmaf(cv1, w1, a0); a0 = fmaf(s1, v1, a0); a0 = fmaf(p1, u1, a0);
                    a1 = fmaf(cv2, w0, a1); a1 = fmaf(s2, v0, a1); a1 = fmaf(p2, u0, a1);
                    a1 = fmaf(cv3, w1, a1); a1 = fmaf(s3, v1, a1); a1 = fmaf(p3, u1, a1);
                    racc[2 * mi] = a0; racc[2 * mi + 1] = a1;
                }
            }
        if (t < NSTEPS) {
            GROUP_BAR(gbar);                     // group's feats(ph_t) written
            gemm3(C, sb, lane, Rbase, n0);       // C += feats @ Wcs^T
            GROUP_BAR(gbar);                     // group done reading feats
        }
    }

    // ---- reduce readout across quad lanes, then across the 4 n-quarter warps ----
#pragma unroll
    for (int q = 0; q < 4; q++) {
        racc[q] += __shfl_xor_sync(0xffffffffu, racc[q], 1);
        racc[q] += __shfl_xor_sync(0xffffffffu, racc[q], 2);
    }
    if ((lane & 3) == 0) {
        atomicAdd(&smf[OFF_OUT / 4 + r0],      racc[0]);
        atomicAdd(&smf[OFF_OUT / 4 + r0 + 8],  racc[1]);
        atomicAdd(&smf[OFF_OUT / 4 + r0 + 16], racc[2]);
        atomicAdd(&smf[OFF_OUT / 4 + r0 + 24], racc[3]);
    }
    __syncthreads();
    if (tid < MROWS)
        outbuf[blockIdx.x * MROWS + tid] = smf[OFF_OUT / 4 + tid] + smf[OFF_RB / 4];
}

extern "C" void kernel_launch(void* const* d_in, const int* in_sizes, int n_in,
                              void* d_out, int out_size) {
    const float* x   = (const float*)d_in[0];
    const float* e_w = (const float*)d_in[1];
    const float* e_b = (const float*)d_in[2];
    const float* d_w = (const float*)d_in[3];
    const float* d_b = (const float*)d_in[4];
    const float* r_w = (const float*)d_in[5];
    const float* r_b = (const float*)d_in[6];
    float* out = (float*)d_out;

    cudaFuncSetAttribute(phase_kernel,
                         cudaFuncAttributeMaxDynamicSharedMemorySize, SMEM_TOTAL);
    phase_kernel<<<NBLK, NTHREADS, SMEM_TOTAL>>>(x, e_w, e_b, d_w, d_b, r_w, r_b, out);
}

// round 14
// speedup vs baseline: 1.2017x; 1.0262x over previous
#include <cuda_runtime.h>
#include <cuda_fp16.h>
#include <cstdint>

#define NROWS   131072
#define HD      128
#define NSTEPS  12
#define MROWS   64
#define NBLK    (NROWS / MROWS)
#define NTHREADS 128
#define HS_STRIDE ((size_t)NROWS * HD)
#define LO_SCALE   1024.0f
#define LO_INV     (1.0f / 1024.0f)

// ---------------- SMEM layout (byte offsets) -------------------------------
// Big tiles: rows x 512 bytes (256 fp16), 16B-chunk swizzle: chunk ^= (row&7)
// K is INTERLEAVED: k' = 2h holds cos/W_cos col h, k' = 2h+1 holds sin/W_sin col h.
#define OFF_WH   0        // W hi fp16: 128(n) x 256(k')    64 KB
#define OFF_WL   65536    // W lo*1024 fp16                 64 KB
#define OFF_FH   131072   // feats hi fp16: 64(m) x 256(k') 32 KB
#define OFF_FL   163840   // feats lo*1024 fp16             32 KB
#define OFF_EW   196608   // e_w (prologue only; overlapped by XDB)
#define OFF_EB   197120   // e_b (prologue only; overlapped by XDB)
#define OFF_XDB  196608   // xdb: 64 slots x 512B ([unit][thread]), 32 KB
#define OFF_DB   229376
#define OFF_K1   229888
#define OFF_OUT  230400
#define OFF_RB   230656
#define SMEM_TOTAL 230672

// ======================= low-level helpers =================================
static __device__ __forceinline__ uint32_t smem_u32(const void* p) {
    uint32_t a;
    asm("{ .reg .u64 t; cvta.to.shared.u64 t, %1; cvt.u32.u64 %0, t; }" : "=r"(a) : "l"(p));
    return a;
}
static __device__ __forceinline__ void ldmx4(uint32_t* a, uint32_t addr) {
    asm volatile("ldmatrix.sync.aligned.m8n8.x4.shared.b16 {%0,%1,%2,%3}, [%4];"
                 : "=r"(a[0]), "=r"(a[1]), "=r"(a[2]), "=r"(a[3]) : "r"(addr));
}
static __device__ __forceinline__ void mma16816(float* c, const uint32_t* a, const uint32_t* b) {
    asm volatile("mma.sync.aligned.m16n8k16.row.col.f32.f16.f16.f32 "
                 "{%0,%1,%2,%3}, {%4,%5,%6,%7}, {%8,%9}, {%0,%1,%2,%3};"
                 : "+f"(c[0]), "+f"(c[1]), "+f"(c[2]), "+f"(c[3])
                 : "r"(a[0]), "r"(a[1]), "r"(a[2]), "r"(a[3]), "r"(b[0]), "r"(b[1]));
}
static __device__ __forceinline__ void mma16816_h(uint32_t* d, const uint32_t* a, const uint32_t* b) {
    asm volatile("mma.sync.aligned.m16n8k16.row.col.f16.f16.f16.f16 "
                 "{%0,%1}, {%2,%3,%4,%5}, {%6,%7}, {%0,%1};"
                 : "+r"(d[0]), "+r"(d[1])
                 : "r"(a[0]), "r"(a[1]), "r"(a[2]), "r"(a[3]), "r"(b[0]), "r"(b[1]));
}

// hi/lo fp16 split of a pair (a -> low half, b -> high half); lo scaled by LO_SCALE
static __device__ __forceinline__ void split2(float a, float b, uint32_t& hi, uint32_t& lo) {
    __half2 h2 = __floats2half2_rn(a, b);
    float2 f2 = __half22float2(h2);
    __half2 l2 = __floats2half2_rn((a - f2.x) * LO_SCALE, (b - f2.y) * LO_SCALE);
    hi = *reinterpret_cast<uint32_t*>(&h2);
    lo = *reinterpret_cast<uint32_t*>(&l2);
}

// 8B store into a swizzled 512B-row tile (cbyte must be 8B-aligned)
static __device__ __forceinline__ void st8sw(char* sm, int off, int r, int cbyte, uint2 v) {
    uint32_t chunk = ((uint32_t)(cbyte >> 4)) ^ (uint32_t)(r & 7);
    *(uint2*)(sm + off + r * 512 + (chunk << 4) + (cbyte & 15)) = v;
}

// Write interleaved (cos,sin) hi+lo for row r, columns cj, cj+1 (cj even):
// bytes [4cj, 4cj+8) = fp16 {c0, s0, c1, s1}.  One STS.64 per tile.
static __device__ __forceinline__ void emit_feats(char* sm, int r, int cj,
                                                  float c0, float c1, float s0, float s1) {
    uint32_t h0, l0, h1, l1;
    split2(c0, s0, h0, l0);
    split2(c1, s1, h1, l1);
    st8sw(sm, OFF_FH, r, 4 * cj, make_uint2(h0, h1));
    st8sw(sm, OFF_FL, r, 4 * cj, make_uint2(l0, l1));
}

// Stage 128x256 fp32 weight block (d_w cols [colbase, colbase+256)) as fp16
// hi + scaled-lo, INTERLEAVED k'. 128 threads: thread = row r = tid.
static __device__ __forceinline__ void stage_w(char* sm, const float* __restrict__ dw,
                                               int colbase, int tid) {
    int r = tid;
    const float* base = dw + (size_t)r * 512 + colbase;
    int rx = r & 7;
    char* dh = sm + OFF_WH + r * 512;
    char* dl = sm + OFF_WL + r * 512;
#pragma unroll 8
    for (int i = 0; i < 32; i++) {
        float4 c = *(const float4*)(base + 4 * i);        // cos cols 4i..4i+3
        float4 s = *(const float4*)(base + 128 + 4 * i);  // sin cols 4i..4i+3
        uint4 h, l;
        split2(c.x, s.x, h.x, l.x);
        split2(c.y, s.y, h.y, l.y);
        split2(c.z, s.z, h.z, l.z);
        split2(c.w, s.w, h.w, l.w);
        uint32_t chunk = (uint32_t)(i ^ rx);
        *(uint4*)(dh + (chunk << 4)) = h;
        *(uint4*)(dl + (chunk << 4)) = l;
    }
}

// ---------------- epilogue unit (shared by plain + fused paths) ------------
// Unit u (0..15): q = u>>2 row sel, jp = u&3 col-pair sel.
template<bool READOUT>
static __device__ __forceinline__ void epi_unit(
    int u, char* smp, float* smf, const float* Ce, int xb, float tm1,
    float* hb, int er0, int n0, int c2, float* racc, const float* __restrict__ rw)
{
    const int q = u >> 2, jp = u & 3;
    const int cj = n0 + jp * 8 + c2;
    const int ci = (q >> 1) * 16 + jp * 4 + (q & 1) * 2;
    float xd0 = smf[xb + (2 * u) * 128];
    float xd1 = smf[xb + (2 * u + 1) * 128];
    float p0 = fmaf(tm1, xd0, Ce[ci]);
    float p1 = fmaf(tm1, xd1, Ce[ci + 1]);
    __stcs((float2*)(hb + q * 8 * HD + cj), make_float2(p0, p1));
    float s0, c0v, s1, c1v;
    __sincosf(p0, &s0, &c0v);
    __sincosf(p1, &s1, &c1v);
    if (!READOUT) {
        emit_feats(smp, er0 + 8 * q, cj, c0v, c1v, s0, s1);
    } else {
        float a = racc[q];
        a = fmaf(c0v, __ldg(rw + cj),       a);
        a = fmaf(s0,  __ldg(rw + 128 + cj), a);
        a = fmaf(p0,  __ldg(rw + 256 + cj), a);
        a = fmaf(c1v, __ldg(rw + cj + 1),       a);
        a = fmaf(s1,  __ldg(rw + 128 + cj + 1), a);
        a = fmaf(p1,  __ldg(rw + 256 + cj + 1), a);
        racc[q] = a;
    }
}

template<bool READOUT>
static __device__ __forceinline__ void plain_epi(
    char* smp, float* smf, const float* Ce, int xb, float tm1,
    float* hb, int er0, int n0, int c2, float* racc, const float* __restrict__ rw)
{
#pragma unroll
    for (int u = 0; u < 16; u++)
        epi_unit<READOUT>(u, smp, smf, Ce, xb, tm1, hb, er0, n0, c2, racc, rw);
}

// ---------------- fused phase: gemm(32x32 tile over block grb) + epilogue --
// Gemm: Cg += feats[grb..grb+31] @ W (3-pass split).  Epilogue: 16 units of the
// OTHER block, one interleaved per kt iteration (static tensor/ALU overlap).
template<bool READOUT>
static __device__ __forceinline__ void fused_phase(
    uint32_t sb, char* smp, float* smf, int lane,
    float* Cg, int grb,
    const float* Ce, int er0, int xb, float tm1, float* hb,
    int n0, int c2, float* racc, const float* __restrict__ rw)
{
    uint32_t Cw[16];
#pragma unroll
    for (int i = 0; i < 16; i++) Cw[i] = 0u;
    const int rx  = lane & 7;
    const int r   = grb + rx + ((lane >> 3) & 1) * 8;
    const int kpa = lane >> 4;
    const int kpb = (lane >> 3) & 1;
    const int jb  = (lane >> 4) & 1;
    const uint32_t aH = sb + OFF_FH + r * 512;
    const uint32_t aL = sb + OFF_FL + r * 512;
    const uint32_t bRow = (uint32_t)((n0 + rx) * 512 + jb * 4096);
    const uint32_t bH = sb + OFF_WH + bRow;
    const uint32_t bL = sb + OFF_WL + bRow;
#pragma unroll
    for (int kt = 0; kt < 16; kt++) {
        uint32_t aoff = (uint32_t)(((2 * kt + kpa) ^ rx) << 4);
        uint32_t boff = (uint32_t)(((2 * kt + kpb) ^ rx) << 4);
        uint32_t ah0[4], ah1[4], al0[4], al1[4];
        ldmx4(ah0, aH + aoff);
        ldmx4(ah1, aH + 8192 + aoff);
        ldmx4(al0, aL + aoff);
        ldmx4(al1, aL + 8192 + aoff);
#pragma unroll
        for (int jp2 = 0; jp2 < 2; jp2++) {
            uint32_t bh[4], bl[4];
            ldmx4(bh, bH + jp2 * 8192 + boff);
            ldmx4(bl, bL + jp2 * 8192 + boff);
            float* c0 = Cg + jp2 * 8;
            float* c1 = Cg + 16 + jp2 * 8;
            uint32_t* w0 = Cw + jp2 * 4;
            uint32_t* w1 = Cw + 8 + jp2 * 4;
            mma16816(c0,     ah0, bh);      mma16816(c0 + 4, ah0, bh + 2);
            mma16816(c1,     ah1, bh);      mma16816(c1 + 4, ah1, bh + 2);
            mma16816_h(w0,     al0, bh);    mma16816_h(w0,     ah0, bl);
            mma16816_h(w0 + 2, al0, bh + 2); mma16816_h(w0 + 2, ah0, bl + 2);
            mma16816_h(w1,     al1, bh);    mma16816_h(w1,     ah1, bl);
            mma16816_h(w1 + 2, al1, bh + 2); mma16816_h(w1 + 2, ah1, bl + 2);
        }
        // interleaved epilogue unit for the other block
        epi_unit<READOUT>(kt, smp, smf, Ce, xb, tm1, hb, er0, n0, c2, racc, rw);
    }
    // fold f16 correction accumulators into Cg
#pragma unroll
    for (int mi = 0; mi < 2; mi++)
#pragma unroll
        for (int j = 0; j < 4; j++) {
            int bi = mi * 16 + j * 4;
            int wi = mi * 8 + (j >> 1) * 4 + (j & 1) * 2;
            float2 f0 = __half22float2(*reinterpret_cast<__half2*>(&Cw[wi]));
            float2 f1 = __half22float2(*reinterpret_cast<__half2*>(&Cw[wi + 1]));
            Cg[bi + 0] = fmaf(f0.x, LO_INV, Cg[bi + 0]);
            Cg[bi + 1] = fmaf(f0.y, LO_INV, Cg[bi + 1]);
            Cg[bi + 2] = fmaf(f1.x, LO_INV, Cg[bi + 2]);
            Cg[bi + 3] = fmaf(f1.y, LO_INV, Cg[bi + 3]);
        }
}

// plain gemm (prologue X0) — same as fused_phase without epilogue
static __device__ __forceinline__ void gemm_plain(uint32_t sb, int lane, float* Cg, int grb, int n0) {
    uint32_t Cw[16];
#pragma unroll
    for (int i = 0; i < 16; i++) Cw[i] = 0u;
    const int rx  = lane & 7;
    const int r   = grb + rx + ((lane >> 3) & 1) * 8;
    const int kpa = lane >> 4;
    const int kpb = (lane >> 3) & 1;
    const int jb  = (lane >> 4) & 1;
    const uint32_t aH = sb + OFF_FH + r * 512;
    const uint32_t aL = sb + OFF_FL + r * 512;
    const uint32_t bRow = (uint32_t)((n0 + rx) * 512 + jb * 4096);
    const uint32_t bH = sb + OFF_WH + bRow;
    const uint32_t bL = sb + OFF_WL + bRow;
#pragma unroll 4
    for (int kt = 0; kt < 16; kt++) {
        uint32_t aoff = (uint32_t)(((2 * kt + kpa) ^ rx) << 4);
        uint32_t boff = (uint32_t)(((2 * kt + kpb) ^ rx) << 4);
        uint32_t ah0[4], ah1[4], al0[4], al1[4];
        ldmx4(ah0, aH + aoff);
        ldmx4(ah1, aH + 8192 + aoff);
        ldmx4(al0, aL + aoff);
        ldmx4(al1, aL + 8192 + aoff);
#pragma unroll
        for (int jp2 = 0; jp2 < 2; jp2++) {
            uint32_t bh[4], bl[4];
            ldmx4(bh, bH + jp2 * 8192 + boff);
            ldmx4(bl, bL + jp2 * 8192 + boff);
            float* c0 = Cg + jp2 * 8;
            float* c1 = Cg + 16 + jp2 * 8;
            uint32_t* w0 = Cw + jp2 * 4;
            uint32_t* w1 = Cw + 8 + jp2 * 4;
            mma16816(c0,     ah0, bh);      mma16816(c0 + 4, ah0, bh + 2);
            mma16816(c1,     ah1, bh);      mma16816(c1 + 4, ah1, bh + 2);
            mma16816_h(w0,     al0, bh);    mma16816_h(w0,     ah0, bl);
            mma16816_h(w0 + 2, al0, bh + 2); mma16816_h(w0 + 2, ah0, bl + 2);
            mma16816_h(w1,     al1, bh);    mma16816_h(w1,     ah1, bl);
            mma16816_h(w1 + 2, al1, bh + 2); mma16816_h(w1 + 2, ah1, bl + 2);
        }
    }
#pragma unroll
    for (int mi = 0; mi < 2; mi++)
#pragma unroll
        for (int j = 0; j < 4; j++) {
            int bi = mi * 16 + j * 4;
            int wi = mi * 8 + (j >> 1) * 4 + (j & 1) * 2;
            float2 f0 = __half22float2(*reinterpret_cast<__half2*>(&Cw[wi]));
            float2 f1 = __half22float2(*reinterpret_cast<__half2*>(&Cw[wi + 1]));
            Cg[bi + 0] = fmaf(f0.x, LO_INV, Cg[bi + 0]);
            Cg[bi + 1] = fmaf(f0.y, LO_INV, Cg[bi + 1]);
            Cg[bi + 2] = fmaf(f1.x, LO_INV, Cg[bi + 2]);
            Cg[bi + 3] = fmaf(f1.y, LO_INV, Cg[bi + 3]);
        }
}

// ======================= kernel ============================================
__global__ void __launch_bounds__(NTHREADS, 1)
phase_kernel(const float* __restrict__ x, const float* __restrict__ e_w,
             const float* __restrict__ e_b, const float* __restrict__ d_w,
             const float* __restrict__ d_b, const float* __restrict__ r_w,
             const float* __restrict__ r_b, float* __restrict__ outbuf) {
    extern __shared__ char sm[];
    float* smf = (float*)sm;
    const int tid  = threadIdx.x;
    const int lane = tid & 31;
    const int warp = tid >> 5;                   // 0..3 = n-quarter
    const int n0 = warp * 32;
    const int g  = lane >> 2;
    const int c2 = (lane & 3) * 2;
    const int growB = blockIdx.x * MROWS;
    const uint32_t sb = smem_u32(sm);
    const int xbA = OFF_XDB / 4 + tid;           // xdb block A base (unit-major)
    const int xbB = OFF_XDB / 4 + 4096 + tid;    // xdb block B base

    // ---- stage small arrays; exact K1 = rowsum(Wcs cos-half) ----
    smf[OFF_DB / 4 + tid] = d_b[tid];
    smf[OFF_EW / 4 + tid] = e_w[tid];
    smf[OFF_EB / 4 + tid] = e_b[tid];
    {
        const float4* wr = (const float4*)(d_w + (size_t)tid * 512);
        float s = 0.f;
#pragma unroll 8
        for (int i = 0; i < 32; i++) {
            float4 v = wr[i];
            s += v.x + v.y + v.z + v.w;
        }
        smf[OFF_K1 / 4 + tid] = s;
    }
    if (tid < MROWS) smf[OFF_OUT / 4 + tid] = 0.f;
    if (tid == 0) smf[OFF_RB / 4] = r_b[0];

    stage_w(sm, d_w, 256, tid);                  // Wx = d_w[:, 256:512] (hi+lo)
    __syncthreads();

    // ---- xp feats: cos/sin(x*e_w + e_b), 8 rows x 8 cols per thread ----
#pragma unroll
    for (int blk = 0; blk < 2; blk++)
#pragma unroll
        for (int q = 0; q < 4; q++) {
            int row = blk * 32 + g + 8 * q;
            float xr = x[growB + row];
#pragma unroll
            for (int jp = 0; jp < 4; jp++) {
                int cj = n0 + jp * 8 + c2;
                float p0 = fmaf(xr, smf[OFF_EW / 4 + cj], smf[OFF_EB / 4 + cj]);
                float p1 = fmaf(xr, smf[OFF_EW / 4 + cj + 1], smf[OFF_EB / 4 + cj + 1]);
                float s0, c0, s1, c1;
                __sincosf(p0, &s0, &c0);
                __sincosf(p1, &s1, &c1);
                emit_feats(sm, row, cj, c0, c1, s0, s1);
            }
        }
    __syncthreads();

    float CA[32], CB[32];
#pragma unroll
    for (int i = 0; i < 32; i++) { CA[i] = 0.f; CB[i] = 0.f; }

    gemm_plain(sb, lane, CA, 0, n0);             // X0 for block A
    gemm_plain(sb, lane, CB, 32, n0);            // X0 for block B
    __syncthreads();                             // feats/Wx reads done

    // xdb = X0 + d_b -> smem (overwrites EW/EB); C <- X0 + K1 + d_b = ph(1)
#pragma unroll
    for (int blk = 0; blk < 2; blk++) {
        float* C = blk ? CB : CA;
        int xb = blk ? xbB : xbA;
#pragma unroll
        for (int u = 0; u < 16; u++) {
            const int q = u >> 2, jp = u & 3;
            const int cj = n0 + jp * 8 + c2;
            const int ci = (q >> 1) * 16 + jp * 4 + (q & 1) * 2;
#pragma unroll
            for (int e = 0; e < 2; e++) {
                float dbv = smf[OFF_DB / 4 + cj + e];
                float k1v = smf[OFF_K1 / 4 + cj + e];
                smf[xb + (2 * u + e) * 128] = C[ci + e] + dbv;
                C[ci + e] += k1v + dbv;
            }
        }
    }

    stage_w(sm, d_w, 0, tid);                    // Wcs = d_w[:, 0:256] (hi+lo)

    float* hst = outbuf + NROWS;                 // Hstack [12, B, 128]
    float raccA[4] = {0.f, 0.f, 0.f, 0.f};
    float raccB[4] = {0.f, 0.f, 0.f, 0.f};

    // epilogue_B(1): ph_B(1) = C_B (tm1=0); store Hstack slice 0; emit feats_B(1)
    {
        float* hb = hst + (size_t)(growB + 32 + g) * HD;
        plain_epi<false>(sm, smf, CB, xbB, 0.f, hb, 32 + g, n0, c2, raccB, r_w);
    }
    __syncthreads();                             // Wcs + feats_B(1) visible

    // ---- ping-pong recurrence: 11 iterations, 2 fused phases each ----
#pragma unroll 1
    for (int t = 1; t <= 11; t++) {
        // phase 1: epilogue_A(t) interleaved with gemm_B (C_B -> C_B(t+1))
        {
            float* hb = hst + (size_t)(t - 1) * HS_STRIDE + (size_t)(growB + g) * HD;
            fused_phase<false>(sb, sm, smf, lane, CB, 32,
                               CA, g, xbA, (float)(t - 1), hb, n0, c2, raccA, r_w);
        }
        __syncthreads();                         // feats_A(t) visible; gemm_B done reading feats_B(t)
        // phase 2: epilogue_B(t+1) interleaved with gemm_A (C_A -> C_A(t+1))
        {
            float* hb = hst + (size_t)t * HS_STRIDE + (size_t)(growB + 32 + g) * HD;
            if (t < 11)
                fused_phase<false>(sb, sm, smf, lane, CA, 0,
                                   CB, 32 + g, xbB, (float)t, hb, n0, c2, raccB, r_w);
            else
                fused_phase<true>(sb, sm, smf, lane, CA, 0,
                                  CB, 32 + g, xbB, (float)t, hb, n0, c2, raccB, r_w);
        }
        __syncthreads();                         // feats_B(t+1) visible; gemm_A done reading feats_A(t)
    }

    // epilogue_A(12): readout
    {
        float* hb = hst + (size_t)11 * HS_STRIDE + (size_t)(growB + g) * HD;
        plain_epi<true>(sm, smf, CA, xbA, 11.f, hb, g, n0, c2, raccA, r_w);
    }

    // ---- reduce readout across quad lanes, then across the 4 warps ----
#pragma unroll
    for (int q = 0; q < 4; q++) {
        raccA[q] += __shfl_xor_sync(0xffffffffu, raccA[q], 1);
        raccA[q] += __shfl_xor_sync(0xffffffffu, raccA[q], 2);
        raccB[q] += __shfl_xor_sync(0xffffffffu, raccB[q], 1);
        raccB[q] += __shfl_xor_sync(0xffffffffu, raccB[q], 2);
    }
    if ((lane & 3) == 0) {
#pragma unroll
        for (int q = 0; q < 4; q++) {
            atomicAdd(&smf[OFF_OUT / 4 + g + 8 * q], raccA[q]);
            atomicAdd(&smf[OFF_OUT / 4 + 32 + g + 8 * q], raccB[q]);
        }
    }
    __syncthreads();
    if (tid < MROWS)
        outbuf[growB + tid] = smf[OFF_OUT / 4 + tid] + smf[OFF_RB / 4];
}

extern "C" void kernel_launch(void* const* d_in, const int* in_sizes, int n_in,
                              void* d_out, int out_size) {
    const float* x   = (const float*)d_in[0];
    const float* e_w = (const float*)d_in[1];
    const float* e_b = (const float*)d_in[2];
    const float* d_w = (const float*)d_in[3];
    const float* d_b = (const float*)d_in[4];
    const float* r_w = (const float*)d_in[5];
    const float* r_b = (const float*)d_in[6];
    float* out = (float*)d_out;

    cudaFuncSetAttribute(phase_kernel,
                         cudaFuncAttributeMaxDynamicSharedMemorySize, SMEM_TOTAL);
    phase_kernel<<<NBLK, NTHREADS, SMEM_TOTAL>>>(x, e_w, e_b, d_w, d_b, r_w, r_b, out);
}